// round 4
// baseline (speedup 1.0000x reference)
#include <cuda_runtime.h>
#include <math.h>
#include <stdint.h>

// Problem constants
constexpr int Bb = 4;
constexpr int Tt = 2048;
constexpr int Cc = 1024;
constexpr int Hh = 16;
constexpr int Dd = 64;
constexpr int FFf = 2048;
constexpr int Mm = Bb * Tt;   // 8192

// ---------------------------------------------------------------------------
// Scratch (device globals; no allocation allowed)
// ---------------------------------------------------------------------------
__device__ float g_h  [(size_t)Mm * Cc];
__device__ float g_qkv[(size_t)Mm * 3 * Cc];
__device__ float g_att[(size_t)Mm * Cc];
__device__ float g_x2 [(size_t)Mm * Cc];
__device__ float g_ff [(size_t)Mm * FFf];

// ---------------------------------------------------------------------------
// Helpers
// ---------------------------------------------------------------------------
__device__ __forceinline__ void mma_tf32(float* c, const uint32_t* a, const uint32_t* b) {
    asm volatile(
        "mma.sync.aligned.m16n8k8.row.col.f32.tf32.tf32.f32 "
        "{%0,%1,%2,%3}, {%4,%5,%6,%7}, {%8,%9}, {%0,%1,%2,%3};\n"
        : "+f"(c[0]), "+f"(c[1]), "+f"(c[2]), "+f"(c[3])
        : "r"(a[0]), "r"(a[1]), "r"(a[2]), "r"(a[3]), "r"(b[0]), "r"(b[1]));
}

__device__ __forceinline__ void cp16(uint32_t saddr, const void* g) {
    asm volatile("cp.async.cg.shared.global [%0], [%1], 16;\n" :: "r"(saddr), "l"(g));
}

__device__ __forceinline__ void ldsm_x4(uint32_t* r, uint32_t addr) {
    asm volatile("ldmatrix.sync.aligned.m8n8.x4.shared.b16 {%0,%1,%2,%3}, [%4];\n"
                 : "=r"(r[0]), "=r"(r[1]), "=r"(r[2]), "=r"(r[3]) : "r"(addr));
}

// round-to-nearest tf32 (zero-mean operand error; truncation bias was the
// source of the 9.4e-4 rel_err)
__device__ __forceinline__ float rna(float x) {
    uint32_t u;
    asm("cvt.rna.tf32.f32 %0, %1;\n" : "=r"(u) : "f"(x));
    return __uint_as_float(u);
}
__device__ __forceinline__ uint32_t rna_bits(float x) {
    uint32_t u;
    asm("cvt.rna.tf32.f32 %0, %1;\n" : "=r"(u) : "f"(x));
    return u;
}

// ---------------------------------------------------------------------------
// LayerNorm: one block per row of 1024, 256 threads. Output is rounded to
// tf32-exact fp32 (it is only ever consumed as a GEMM A operand).
// ---------------------------------------------------------------------------
__global__ void ln_kernel(const float* __restrict__ x,
                          const float* __restrict__ gamma,
                          const float* __restrict__ beta,
                          float* __restrict__ out) {
    int row = blockIdx.x;
    int tid = threadIdx.x;
    const float4* xr = (const float4*)(x + (size_t)row * Cc);
    float4 v = xr[tid];

    float s  = v.x + v.y + v.z + v.w;
    float sq = v.x * v.x + v.y * v.y + v.z * v.z + v.w * v.w;
    #pragma unroll
    for (int o = 16; o > 0; o >>= 1) {
        s  += __shfl_xor_sync(0xffffffffu, s,  o);
        sq += __shfl_xor_sync(0xffffffffu, sq, o);
    }
    __shared__ float ss[8], ssq[8];
    __shared__ float mu_s, rs_s;
    int w = tid >> 5;
    if ((tid & 31) == 0) { ss[w] = s; ssq[w] = sq; }
    __syncthreads();
    if (tid == 0) {
        float S = 0.f, SQ = 0.f;
        #pragma unroll
        for (int i = 0; i < 8; i++) { S += ss[i]; SQ += ssq[i]; }
        float mu  = S * (1.0f / (float)Cc);
        float var = SQ * (1.0f / (float)Cc) - mu * mu;
        mu_s = mu;
        rs_s = rsqrtf(var + 1e-5f);
    }
    __syncthreads();
    float mu = mu_s, rs = rs_s;
    float4 gv = ((const float4*)gamma)[tid];
    float4 bv = ((const float4*)beta)[tid];
    float4 o4;
    o4.x = rna((v.x - mu) * rs * gv.x + bv.x);
    o4.y = rna((v.y - mu) * rs * gv.y + bv.y);
    o4.z = rna((v.z - mu) * rs * gv.z + bv.z);
    o4.w = rna((v.w - mu) * rs * gv.w + bv.w);
    ((float4*)(out + (size_t)row * Cc))[tid] = o4;
}

// ---------------------------------------------------------------------------
// tf32 tensor-core GEMM: C[M,N] = A[M,K] @ B[K,N]  (+bias/residual/gelu)
// BM=256, BN=128, BK=32, 512 threads = 16 warps (4x4 grid of 64x32 warp
// tiles). 3-stage cp.async. A-fragments via ldmatrix.x4 (b16 trick for tf32).
// A operands are pre-rounded by producers; B (weights) rounded at frag load.
// EPI: 0 = round-out (qkv), 1 = +bias+residual fp32, 2 = +bias, GELU, round.
// ---------------------------------------------------------------------------
constexpr int AS_STRIDE = 36;
constexpr int BS_STRIDE = 136;
constexpr int ASZ = 256 * AS_STRIDE;                // 9216 floats / stage
constexpr int BSZ = 32 * BS_STRIDE;                 // 4352 floats / stage
constexpr int GEMM_SMEM = 3 * (ASZ + BSZ) * 4;      // 162816 bytes

template <int EPI>
__global__ __launch_bounds__(512, 1) void tgemm(
    const float* __restrict__ A, const float* __restrict__ Bm,
    const float* __restrict__ bias, const float* __restrict__ res,
    float* __restrict__ Cout, int Mn, int Nn, int Kn) {
    extern __shared__ float smem_g[];
    float* AsB = smem_g;
    float* BsB = smem_g + 3 * ASZ;

    int tid = threadIdx.x, lane = tid & 31, w = tid >> 5;
    int wm = w >> 2, wn = w & 3;           // 4 x 4 warp grid
    int row0 = blockIdx.y * 256, col0 = blockIdx.x * 128;
    int r = lane >> 2, c = lane & 3;

    float acc[4][4][4];
    #pragma unroll
    for (int i = 0; i < 4; i++)
        #pragma unroll
        for (int j = 0; j < 4; j++)
            #pragma unroll
            for (int k = 0; k < 4; k++) acc[i][j][k] = 0.f;

    uint32_t asBase = (uint32_t)__cvta_generic_to_shared(AsB);
    uint32_t bsBase = (uint32_t)__cvta_generic_to_shared(BsB);

    // ldmatrix lane geometry for A-frags (mat: 0..3 -> a0..a3)
    int arow = ((lane >> 3) & 1) * 8 + (lane & 7);
    int acol = (lane >> 4) * 4;
    uint32_t aLaneOff = (uint32_t)(arow * AS_STRIDE + acol) * 4u;

    auto loadA = [&](int st, int k0) {
        #pragma unroll
        for (int i = 0; i < 4; i++) {
            int p = tid + i * 512;
            int rr = p >> 3, c4 = p & 7;
            uint32_t sa = asBase + (uint32_t)(st * ASZ + rr * AS_STRIDE + c4 * 4) * 4u;
            cp16(sa, A + (size_t)(row0 + rr) * Kn + k0 + c4 * 4);
        }
    };
    auto loadB = [&](int st, int k0) {
        #pragma unroll
        for (int i = 0; i < 2; i++) {
            int p = tid + i * 512;
            int rr = p >> 5, c4 = p & 31;
            uint32_t sa = bsBase + (uint32_t)(st * BSZ + rr * BS_STRIDE + c4 * 4) * 4u;
            cp16(sa, Bm + (size_t)(k0 + rr) * Nn + col0 + c4 * 4);
        }
    };

    int nk = Kn >> 5;
    loadA(0, 0); loadB(0, 0);
    asm volatile("cp.async.commit_group;\n" ::: "memory");
    loadA(1, 32); loadB(1, 32);
    asm volatile("cp.async.commit_group;\n" ::: "memory");

    for (int kt = 0; kt < nk; kt++) {
        int st = kt % 3;
        asm volatile("cp.async.wait_group 1;\n" ::: "memory");
        __syncthreads();
        if (kt + 2 < nk) {
            int st2 = (kt + 2) % 3;
            loadA(st2, (kt + 2) * 32); loadB(st2, (kt + 2) * 32);
        }
        asm volatile("cp.async.commit_group;\n" ::: "memory");

        const float* Bsp = BsB + st * BSZ;
        uint32_t aStage = asBase + (uint32_t)(st * ASZ) * 4u + aLaneOff;
        #pragma unroll
        for (int kk = 0; kk < 4; kk++) {
            int k = kk * 8;
            uint32_t af[4][4], bf[4][2];
            #pragma unroll
            for (int mi = 0; mi < 4; mi++)
                ldsm_x4(af[mi], aStage + (uint32_t)((wm * 64 + mi * 16) * AS_STRIDE + k) * 4u);
            #pragma unroll
            for (int ni = 0; ni < 4; ni++) {
                int n0 = wn * 32 + ni * 8;
                bf[ni][0] = rna_bits(Bsp[(k + c) * BS_STRIDE + n0 + r]);
                bf[ni][1] = rna_bits(Bsp[(k + c + 4) * BS_STRIDE + n0 + r]);
            }
            #pragma unroll
            for (int mi = 0; mi < 4; mi++)
                #pragma unroll
                for (int ni = 0; ni < 4; ni++)
                    mma_tf32(acc[mi][ni], af[mi], bf[ni]);
        }
        __syncthreads();
    }

    // Epilogue: C fragment rows r/r+8, cols 2c/2c+1
    #pragma unroll
    for (int mi = 0; mi < 4; mi++) {
        int rr0 = row0 + wm * 64 + mi * 16 + r;
        #pragma unroll
        for (int ni = 0; ni < 4; ni++) {
            int cc = col0 + wn * 32 + ni * 8 + 2 * c;
            float v0 = acc[mi][ni][0], v1 = acc[mi][ni][1];
            float v2 = acc[mi][ni][2], v3 = acc[mi][ni][3];
            if (EPI == 0) {
                v0 = rna(v0); v1 = rna(v1); v2 = rna(v2); v3 = rna(v3);
            } else if (EPI == 1) {
                float b0 = bias[cc], b1 = bias[cc + 1];
                float2 r0 = *(const float2*)&res[(size_t)rr0 * Nn + cc];
                float2 r1 = *(const float2*)&res[(size_t)(rr0 + 8) * Nn + cc];
                v0 += b0 + r0.x; v1 += b1 + r0.y;
                v2 += b0 + r1.x; v3 += b1 + r1.y;
            } else {
                float b0 = bias[cc], b1 = bias[cc + 1];
                v0 += b0; v1 += b1; v2 += b0; v3 += b1;
                v0 = rna(0.5f * v0 * (1.0f + erff(v0 * 0.70710678118654752f)));
                v1 = rna(0.5f * v1 * (1.0f + erff(v1 * 0.70710678118654752f)));
                v2 = rna(0.5f * v2 * (1.0f + erff(v2 * 0.70710678118654752f)));
                v3 = rna(0.5f * v3 * (1.0f + erff(v3 * 0.70710678118654752f)));
            }
            *(float2*)&Cout[(size_t)rr0 * Nn + cc]       = make_float2(v0, v1);
            *(float2*)&Cout[(size_t)(rr0 + 8) * Nn + cc] = make_float2(v2, v3);
        }
    }
}

// ---------------------------------------------------------------------------
// Tensor-core flash attention with permutation mask.
// 128 queries/block (8 warps x 16 rows), KV tiles of 64, D=64.
// Q in registers; K-frags and P-frags via ldmatrix.x4; V via conflict-free
// LDS.32. Q/K/V are tf32-exact on entry (qkv epilogue rounds); P rounded
// after exp; output rounded (only consumed as GEMM A operand).
// ---------------------------------------------------------------------------
constexpr int KSS = 68;
constexpr int VSS = 72;
constexpr int PSS = 68;
constexpr int KS_F = 64 * KSS;
constexpr int VS_F = 64 * VSS;
constexpr int PS_F = 128 * PSS;
constexpr int ATTN_SMEM = (KS_F + VS_F + PS_F) * 4 + 64 * 4;  // 70912 B

__global__ __launch_bounds__(256, 2) void attn_mma(
    const float* __restrict__ qkv, const int* __restrict__ perm,
    float* __restrict__ out) {
    extern __shared__ float smem_a[];
    float* Ks = smem_a;
    float* Vs = Ks + KS_F;
    float* Ps = Vs + VS_F;
    int*   permS = (int*)(Ps + PS_F);

    int tid = threadIdx.x, lane = tid & 31, w = tid >> 5;
    int r = lane >> 2, c = lane & 3;
    int q0 = blockIdx.x * 128;
    int h = blockIdx.y, b = blockIdx.z;

    uint32_t ksBase = (uint32_t)__cvta_generic_to_shared(Ks);
    uint32_t psBase = (uint32_t)__cvta_generic_to_shared(Ps);

    // ldmatrix lane geometry
    int keyoff = ((lane >> 4) << 3) + (lane & 7);        // K-frags (B-op pairs)
    int dhalf  = ((lane >> 3) & 1) * 4;
    int prow   = ((lane >> 3) & 1) * 8 + (lane & 7);     // P-frags (A-op)
    int pcol   = (lane >> 4) * 4;

    // Load Q fragments once (values already tf32-exact)
    const float* qb = qkv + ((size_t)(b * Tt + q0 + w * 16)) * 3072 + h * 64;
    uint32_t qa[8][4];
    #pragma unroll
    for (int j = 0; j < 8; j++) {
        qa[j][0] = __float_as_uint(qb[(size_t)r * 3072 + j * 8 + c]);
        qa[j][1] = __float_as_uint(qb[(size_t)(r + 8) * 3072 + j * 8 + c]);
        qa[j][2] = __float_as_uint(qb[(size_t)r * 3072 + j * 8 + c + 4]);
        qa[j][3] = __float_as_uint(qb[(size_t)(r + 8) * 3072 + j * 8 + c + 4]);
    }

    float oacc[8][4];
    #pragma unroll
    for (int i = 0; i < 8; i++)
        #pragma unroll
        for (int k = 0; k < 4; k++) oacc[i][k] = 0.f;
    float m0 = -1e30f, m1 = -1e30f, l0 = 0.f, l1 = 0.f;
    int q_lo = q0 + w * 16 + r, q_hi = q_lo + 8;
    float* Pw = Ps + (w * 16) * PSS;
    uint32_t pwBase = psBase + (uint32_t)((w * 16) * PSS) * 4u;

    for (int k0 = 0; k0 < Tt; k0 += 64) {
        __syncthreads();
        #pragma unroll
        for (int i = 0; i < 4; i++) {
            int p = tid + i * 256;
            int kr = p >> 4, c4 = p & 15;
            const float* gk = qkv + ((size_t)(b * Tt + k0 + kr)) * 3072 + 1024 + h * 64 + c4 * 4;
            float4 kx = *(const float4*)gk;
            *(float4*)&Ks[kr * KSS + c4 * 4] = kx;
            float4 vx = *(const float4*)(gk + 1024);
            *(float4*)&Vs[kr * VSS + c4 * 4] = vx;
        }
        if (tid < 64) permS[tid] = perm[k0 + tid];
        __syncthreads();

        // S = Q @ K^T : K-frags via ldmatrix (ni pairs)
        float sacc[8][4];
        #pragma unroll
        for (int i = 0; i < 8; i++)
            #pragma unroll
            for (int k = 0; k < 4; k++) sacc[i][k] = 0.f;
        #pragma unroll
        for (int j = 0; j < 8; j++) {
            #pragma unroll
            for (int np = 0; np < 4; np++) {
                uint32_t kb[4];
                ldsm_x4(kb, ksBase + (uint32_t)((np * 16 + keyoff) * KSS + j * 8 + dhalf) * 4u);
                mma_tf32(sacc[np * 2],     qa[j], kb);
                mma_tf32(sacc[np * 2 + 1], qa[j], kb + 2);
            }
        }

        // Mask + scale + per-row max
        float mx0 = -1e30f, mx1 = -1e30f;
        #pragma unroll
        for (int ni = 0; ni < 8; ni++) {
            int col = ni * 8 + 2 * c;
            int p0 = permS[col], p1 = permS[col + 1];
            sacc[ni][0] = (p0 > q_lo) ? -1e30f : sacc[ni][0] * 0.125f;
            sacc[ni][1] = (p1 > q_lo) ? -1e30f : sacc[ni][1] * 0.125f;
            sacc[ni][2] = (p0 > q_hi) ? -1e30f : sacc[ni][2] * 0.125f;
            sacc[ni][3] = (p1 > q_hi) ? -1e30f : sacc[ni][3] * 0.125f;
            mx0 = fmaxf(mx0, fmaxf(sacc[ni][0], sacc[ni][1]));
            mx1 = fmaxf(mx1, fmaxf(sacc[ni][2], sacc[ni][3]));
        }
        mx0 = fmaxf(mx0, __shfl_xor_sync(0xffffffffu, mx0, 1));
        mx0 = fmaxf(mx0, __shfl_xor_sync(0xffffffffu, mx0, 2));
        mx1 = fmaxf(mx1, __shfl_xor_sync(0xffffffffu, mx1, 1));
        mx1 = fmaxf(mx1, __shfl_xor_sync(0xffffffffu, mx1, 2));

        float nm0 = fmaxf(m0, mx0), nm1 = fmaxf(m1, mx1);
        float al0 = __expf(m0 - nm0), al1 = __expf(m1 - nm1);
        float ls0 = 0.f, ls1 = 0.f;
        #pragma unroll
        for (int ni = 0; ni < 8; ni++) {
            sacc[ni][0] = rna(__expf(sacc[ni][0] - nm0));
            sacc[ni][1] = rna(__expf(sacc[ni][1] - nm0));
            sacc[ni][2] = rna(__expf(sacc[ni][2] - nm1));
            sacc[ni][3] = rna(__expf(sacc[ni][3] - nm1));
            ls0 += sacc[ni][0] + sacc[ni][1];
            ls1 += sacc[ni][2] + sacc[ni][3];
        }
        ls0 += __shfl_xor_sync(0xffffffffu, ls0, 1);
        ls0 += __shfl_xor_sync(0xffffffffu, ls0, 2);
        ls1 += __shfl_xor_sync(0xffffffffu, ls1, 1);
        ls1 += __shfl_xor_sync(0xffffffffu, ls1, 2);
        l0 = l0 * al0 + ls0;
        l1 = l1 * al1 + ls1;
        m0 = nm0; m1 = nm1;
        #pragma unroll
        for (int ni = 0; ni < 8; ni++) {
            oacc[ni][0] *= al0; oacc[ni][1] *= al0;
            oacc[ni][2] *= al1; oacc[ni][3] *= al1;
        }

        // Write rounded P to per-warp smem (C-frag layout)
        #pragma unroll
        for (int ni = 0; ni < 8; ni++) {
            int col = ni * 8 + 2 * c;
            *(float2*)&Pw[r * PSS + col]       = make_float2(sacc[ni][0], sacc[ni][1]);
            *(float2*)&Pw[(r + 8) * PSS + col] = make_float2(sacc[ni][2], sacc[ni][3]);
        }
        __syncwarp();

        // O += P @ V : P-frags via ldmatrix, V via conflict-free LDS.32
        #pragma unroll
        for (int j = 0; j < 8; j++) {
            uint32_t pa[4];
            ldsm_x4(pa, pwBase + (uint32_t)(prow * PSS + j * 8 + pcol) * 4u);
            #pragma unroll
            for (int ni = 0; ni < 8; ni++) {
                uint32_t vb[2];
                vb[0] = __float_as_uint(Vs[(j * 8 + c) * VSS + ni * 8 + r]);
                vb[1] = __float_as_uint(Vs[(j * 8 + c + 4) * VSS + ni * 8 + r]);
                mma_tf32(oacc[ni], pa, vb);
            }
        }
    }

    float inv0 = 1.0f / l0, inv1 = 1.0f / l1;
    float* ob = out + ((size_t)(b * Tt + q_lo)) * 1024 + h * 64;
    #pragma unroll
    for (int ni = 0; ni < 8; ni++) {
        int col = ni * 8 + 2 * c;
        *(float2*)&ob[col] = make_float2(rna(oacc[ni][0] * inv0), rna(oacc[ni][1] * inv0));
        *(float2*)&ob[(size_t)8 * 1024 + col] =
            make_float2(rna(oacc[ni][2] * inv1), rna(oacc[ni][3] * inv1));
    }
}

// ---------------------------------------------------------------------------
// Launch
// ---------------------------------------------------------------------------
extern "C" void kernel_launch(void* const* d_in, const int* in_sizes, int n_in,
                              void* d_out, int out_size) {
    (void)in_sizes; (void)n_in; (void)out_size;
    const float* x     = (const float*)d_in[0];
    const int*   perm  = (const int*)d_in[1];
    const float* Wqkv  = (const float*)d_in[2];
    const float* Wproj = (const float*)d_in[3];
    const float* bproj = (const float*)d_in[4];
    const float* ln1_g = (const float*)d_in[5];
    const float* ln1_b = (const float*)d_in[6];
    const float* ln2_g = (const float*)d_in[7];
    const float* ln2_b = (const float*)d_in[8];
    const float* Wff1  = (const float*)d_in[9];
    const float* bff1  = (const float*)d_in[10];
    const float* Wff2  = (const float*)d_in[11];
    const float* bff2  = (const float*)d_in[12];
    float* out = (float*)d_out;

    void *ph, *pqkv, *patt, *px2, *pff;
    cudaGetSymbolAddress(&ph,   g_h);
    cudaGetSymbolAddress(&pqkv, g_qkv);
    cudaGetSymbolAddress(&patt, g_att);
    cudaGetSymbolAddress(&px2,  g_x2);
    cudaGetSymbolAddress(&pff,  g_ff);
    float* h   = (float*)ph;
    float* qkv = (float*)pqkv;
    float* att = (float*)patt;
    float* x2  = (float*)px2;
    float* ff  = (float*)pff;

    cudaFuncSetAttribute((const void*)tgemm<0>,
                         cudaFuncAttributeMaxDynamicSharedMemorySize, GEMM_SMEM);
    cudaFuncSetAttribute((const void*)tgemm<1>,
                         cudaFuncAttributeMaxDynamicSharedMemorySize, GEMM_SMEM);
    cudaFuncSetAttribute((const void*)tgemm<2>,
                         cudaFuncAttributeMaxDynamicSharedMemorySize, GEMM_SMEM);
    cudaFuncSetAttribute((const void*)attn_mma,
                         cudaFuncAttributeMaxDynamicSharedMemorySize, ATTN_SMEM);

    // 1. h = LN1(x)                       (output tf32-rounded)
    ln_kernel<<<Mm, 256>>>(x, ln1_g, ln1_b, h);
    // 2. qkv = h @ Wqkv                   (output tf32-rounded)
    tgemm<0><<<dim3(3 * Cc / 128, Mm / 256), 512, GEMM_SMEM>>>(
        h, Wqkv, nullptr, nullptr, qkv, Mm, 3 * Cc, Cc);
    // 3. attention -> att                 (output tf32-rounded)
    attn_mma<<<dim3(Tt / 128, Hh, Bb), 256, ATTN_SMEM>>>(qkv, perm, att);
    // 4. x2 = x + att @ Wproj + bproj     (full fp32 residual)
    tgemm<1><<<dim3(Cc / 128, Mm / 256), 512, GEMM_SMEM>>>(
        att, Wproj, bproj, x, x2, Mm, Cc, Cc);
    // 5. h = LN2(x2)                      (output tf32-rounded)
    ln_kernel<<<Mm, 256>>>(x2, ln2_g, ln2_b, h);
    // 6. ff = gelu(h @ Wff1 + bff1)       (output tf32-rounded)
    tgemm<2><<<dim3(FFf / 128, Mm / 256), 512, GEMM_SMEM>>>(
        h, Wff1, bff1, nullptr, ff, Mm, FFf, Cc);
    // 7. out = x2 + ff @ Wff2 + bff2      (full fp32 residual)
    tgemm<1><<<dim3(Cc / 128, Mm / 256), 512, GEMM_SMEM>>>(
        ff, Wff2, bff2, x2, out, Mm, Cc, FFf);
}

// round 8
// speedup vs baseline: 1.7392x; 1.7392x over previous
#include <cuda_runtime.h>
#include <math.h>
#include <stdint.h>

// Problem constants
constexpr int Bb = 4;
constexpr int Tt = 2048;
constexpr int Cc = 1024;
constexpr int Hh = 16;
constexpr int Dd = 64;
constexpr int FFf = 2048;
constexpr int Mm = Bb * Tt;   // 8192

// ---------------------------------------------------------------------------
// Scratch (device globals; no allocation allowed)
// ---------------------------------------------------------------------------
__device__ float g_h   [(size_t)Mm * Cc];
__device__ float g_qkv [(size_t)Mm * 3 * Cc];
__device__ float g_att [(size_t)Mm * Cc];
__device__ float g_x2  [(size_t)Mm * Cc];
__device__ float g_ff  [(size_t)Mm * FFf];
// tf32-rounded weight copies (rounded once per launch; keeps CVT out of loops)
__device__ float g_wqkv [(size_t)Cc * 3 * Cc];
__device__ float g_wproj[(size_t)Cc * Cc];
__device__ float g_wff1 [(size_t)Cc * FFf];
__device__ float g_wff2 [(size_t)FFf * Cc];

// ---------------------------------------------------------------------------
// Helpers
// ---------------------------------------------------------------------------
__device__ __forceinline__ void mma_tf32(float* c, const uint32_t* a, const uint32_t* b) {
    asm volatile(
        "mma.sync.aligned.m16n8k8.row.col.f32.tf32.tf32.f32 "
        "{%0,%1,%2,%3}, {%4,%5,%6,%7}, {%8,%9}, {%0,%1,%2,%3};\n"
        : "+f"(c[0]), "+f"(c[1]), "+f"(c[2]), "+f"(c[3])
        : "r"(a[0]), "r"(a[1]), "r"(a[2]), "r"(a[3]), "r"(b[0]), "r"(b[1]));
}

__device__ __forceinline__ void cp16(uint32_t saddr, const void* g) {
    asm volatile("cp.async.cg.shared.global [%0], [%1], 16;\n" :: "r"(saddr), "l"(g));
}

__device__ __forceinline__ void ldsm_x4(uint32_t* r, uint32_t addr) {
    asm volatile("ldmatrix.sync.aligned.m8n8.x4.shared.b16 {%0,%1,%2,%3}, [%4];\n"
                 : "=r"(r[0]), "=r"(r[1]), "=r"(r[2]), "=r"(r[3]) : "r"(addr));
}

// round-to-nearest tf32 (zero-mean operand error)
__device__ __forceinline__ float rna(float x) {
    uint32_t u;
    asm("cvt.rna.tf32.f32 %0, %1;\n" : "=r"(u) : "f"(x));
    return __uint_as_float(u);
}

// ---------------------------------------------------------------------------
// Weight pre-rounding: one grid-stride float4 pass
// ---------------------------------------------------------------------------
__global__ void round_w_kernel(const float* __restrict__ src,
                               float* __restrict__ dst, int n4) {
    int i = blockIdx.x * blockDim.x + threadIdx.x;
    if (i < n4) {
        float4 v = ((const float4*)src)[i];
        v.x = rna(v.x); v.y = rna(v.y); v.z = rna(v.z); v.w = rna(v.w);
        ((float4*)dst)[i] = v;
    }
}

// ---------------------------------------------------------------------------
// LayerNorm: one block per row of 1024, 256 threads; tf32-rounded output.
// ---------------------------------------------------------------------------
__global__ void ln_kernel(const float* __restrict__ x,
                          const float* __restrict__ gamma,
                          const float* __restrict__ beta,
                          float* __restrict__ out) {
    int row = blockIdx.x;
    int tid = threadIdx.x;
    const float4* xr = (const float4*)(x + (size_t)row * Cc);
    float4 v = xr[tid];

    float s  = v.x + v.y + v.z + v.w;
    float sq = v.x * v.x + v.y * v.y + v.z * v.z + v.w * v.w;
    #pragma unroll
    for (int o = 16; o > 0; o >>= 1) {
        s  += __shfl_xor_sync(0xffffffffu, s,  o);
        sq += __shfl_xor_sync(0xffffffffu, sq, o);
    }
    __shared__ float ss[8], ssq[8];
    __shared__ float mu_s, rs_s;
    int w = tid >> 5;
    if ((tid & 31) == 0) { ss[w] = s; ssq[w] = sq; }
    __syncthreads();
    if (tid == 0) {
        float S = 0.f, SQ = 0.f;
        #pragma unroll
        for (int i = 0; i < 8; i++) { S += ss[i]; SQ += ssq[i]; }
        float mu  = S * (1.0f / (float)Cc);
        float var = SQ * (1.0f / (float)Cc) - mu * mu;
        mu_s = mu;
        rs_s = rsqrtf(var + 1e-5f);
    }
    __syncthreads();
    float mu = mu_s, rs = rs_s;
    float4 gv = ((const float4*)gamma)[tid];
    float4 bv = ((const float4*)beta)[tid];
    float4 o4;
    o4.x = rna((v.x - mu) * rs * gv.x + bv.x);
    o4.y = rna((v.y - mu) * rs * gv.y + bv.y);
    o4.z = rna((v.z - mu) * rs * gv.z + bv.z);
    o4.w = rna((v.w - mu) * rs * gv.w + bv.w);
    ((float4*)(out + (size_t)row * Cc))[tid] = o4;
}

// ---------------------------------------------------------------------------
// tf32 tensor-core GEMM: C[M,N] = A[M,K] @ B[K,N]  (+bias/residual/gelu)
// BM=BN=128, BK=32, 256 threads = 8 warps (2x4 grid of 64x32 warp tiles).
// 3-stage cp.async, 2 CTAs/SM. A-frags via ldmatrix.x4; B-frags raw LDS
// (operands pre-rounded by producers / weight pre-pass).
// EPI: 0 = round-out (qkv), 1 = +bias+residual fp32, 2 = +bias, GELU, round.
// ---------------------------------------------------------------------------
constexpr int AS_STRIDE = 36;
constexpr int BS_STRIDE = 136;
constexpr int ASZ = 128 * AS_STRIDE;                // 4608 floats / stage
constexpr int BSZ = 32 * BS_STRIDE;                 // 4352 floats / stage
constexpr int GEMM_SMEM = 3 * (ASZ + BSZ) * 4;      // 107520 bytes

template <int EPI>
__global__ __launch_bounds__(256, 2) void tgemm(
    const float* __restrict__ A, const float* __restrict__ Bm,
    const float* __restrict__ bias, const float* __restrict__ res,
    float* __restrict__ Cout, int Mn, int Nn, int Kn) {
    extern __shared__ float smem_g[];
    float* AsB = smem_g;
    float* BsB = smem_g + 3 * ASZ;

    int tid = threadIdx.x, lane = tid & 31, w = tid >> 5;
    int wm = w >> 2, wn = w & 3;           // 2 x 4 warp grid
    int row0 = blockIdx.y * 128, col0 = blockIdx.x * 128;
    int r = lane >> 2, c = lane & 3;

    float acc[4][4][4];
    #pragma unroll
    for (int i = 0; i < 4; i++)
        #pragma unroll
        for (int j = 0; j < 4; j++)
            #pragma unroll
            for (int k = 0; k < 4; k++) acc[i][j][k] = 0.f;

    uint32_t asBase = (uint32_t)__cvta_generic_to_shared(AsB);
    uint32_t bsBase = (uint32_t)__cvta_generic_to_shared(BsB);

    // ldmatrix lane geometry for A-frags
    int arow = ((lane >> 3) & 1) * 8 + (lane & 7);
    int acol = (lane >> 4) * 4;
    uint32_t aLaneOff = (uint32_t)(arow * AS_STRIDE + acol) * 4u;

    auto loadA = [&](int st, int k0) {
        #pragma unroll
        for (int i = 0; i < 4; i++) {
            int p = tid + i * 256;
            int rr = p >> 3, c4 = p & 7;
            uint32_t sa = asBase + (uint32_t)(st * ASZ + rr * AS_STRIDE + c4 * 4) * 4u;
            cp16(sa, A + (size_t)(row0 + rr) * Kn + k0 + c4 * 4);
        }
    };
    auto loadB = [&](int st, int k0) {
        #pragma unroll
        for (int i = 0; i < 4; i++) {
            int p = tid + i * 256;
            int rr = p >> 5, c4 = p & 31;
            uint32_t sa = bsBase + (uint32_t)(st * BSZ + rr * BS_STRIDE + c4 * 4) * 4u;
            cp16(sa, Bm + (size_t)(k0 + rr) * Nn + col0 + c4 * 4);
        }
    };

    int nk = Kn >> 5;
    loadA(0, 0); loadB(0, 0);
    asm volatile("cp.async.commit_group;\n" ::: "memory");
    loadA(1, 32); loadB(1, 32);
    asm volatile("cp.async.commit_group;\n" ::: "memory");

    for (int kt = 0; kt < nk; kt++) {
        int st = kt % 3;
        asm volatile("cp.async.wait_group 1;\n" ::: "memory");
        __syncthreads();
        if (kt + 2 < nk) {
            int st2 = (kt + 2) % 3;
            loadA(st2, (kt + 2) * 32); loadB(st2, (kt + 2) * 32);
        }
        asm volatile("cp.async.commit_group;\n" ::: "memory");

        const float* Bsp = BsB + st * BSZ;
        uint32_t aStage = asBase + (uint32_t)(st * ASZ) * 4u + aLaneOff;
        #pragma unroll
        for (int kk = 0; kk < 4; kk++) {
            int k = kk * 8;
            uint32_t af[4][4], bf[4][2];
            #pragma unroll
            for (int mi = 0; mi < 4; mi++)
                ldsm_x4(af[mi], aStage + (uint32_t)((wm * 64 + mi * 16) * AS_STRIDE + k) * 4u);
            #pragma unroll
            for (int ni = 0; ni < 4; ni++) {
                int n0 = wn * 32 + ni * 8;
                bf[ni][0] = __float_as_uint(Bsp[(k + c) * BS_STRIDE + n0 + r]);
                bf[ni][1] = __float_as_uint(Bsp[(k + c + 4) * BS_STRIDE + n0 + r]);
            }
            #pragma unroll
            for (int mi = 0; mi < 4; mi++)
                #pragma unroll
                for (int ni = 0; ni < 4; ni++)
                    mma_tf32(acc[mi][ni], af[mi], bf[ni]);
        }
        __syncthreads();
    }

    #pragma unroll
    for (int mi = 0; mi < 4; mi++) {
        int rr0 = row0 + wm * 64 + mi * 16 + r;
        #pragma unroll
        for (int ni = 0; ni < 4; ni++) {
            int cc = col0 + wn * 32 + ni * 8 + 2 * c;
            float v0 = acc[mi][ni][0], v1 = acc[mi][ni][1];
            float v2 = acc[mi][ni][2], v3 = acc[mi][ni][3];
            if (EPI == 0) {
                v0 = rna(v0); v1 = rna(v1); v2 = rna(v2); v3 = rna(v3);
            } else if (EPI == 1) {
                float b0 = bias[cc], b1 = bias[cc + 1];
                float2 r0 = *(const float2*)&res[(size_t)rr0 * Nn + cc];
                float2 r1 = *(const float2*)&res[(size_t)(rr0 + 8) * Nn + cc];
                v0 += b0 + r0.x; v1 += b1 + r0.y;
                v2 += b0 + r1.x; v3 += b1 + r1.y;
            } else {
                float b0 = bias[cc], b1 = bias[cc + 1];
                v0 += b0; v1 += b1; v2 += b0; v3 += b1;
                v0 = rna(0.5f * v0 * (1.0f + erff(v0 * 0.70710678118654752f)));
                v1 = rna(0.5f * v1 * (1.0f + erff(v1 * 0.70710678118654752f)));
                v2 = rna(0.5f * v2 * (1.0f + erff(v2 * 0.70710678118654752f)));
                v3 = rna(0.5f * v3 * (1.0f + erff(v3 * 0.70710678118654752f)));
            }
            *(float2*)&Cout[(size_t)rr0 * Nn + cc]       = make_float2(v0, v1);
            *(float2*)&Cout[(size_t)(rr0 + 8) * Nn + cc] = make_float2(v2, v3);
        }
    }
}

// ---------------------------------------------------------------------------
// Tensor-core flash attention with permutation mask (unchanged from R4).
// ---------------------------------------------------------------------------
constexpr int KSS = 68;
constexpr int VSS = 72;
constexpr int PSS = 68;
constexpr int KS_F = 64 * KSS;
constexpr int VS_F = 64 * VSS;
constexpr int PS_F = 128 * PSS;
constexpr int ATTN_SMEM = (KS_F + VS_F + PS_F) * 4 + 64 * 4;  // 70912 B

__global__ __launch_bounds__(256, 2) void attn_mma(
    const float* __restrict__ qkv, const int* __restrict__ perm,
    float* __restrict__ out) {
    extern __shared__ float smem_a[];
    float* Ks = smem_a;
    float* Vs = Ks + KS_F;
    float* Ps = Vs + VS_F;
    int*   permS = (int*)(Ps + PS_F);

    int tid = threadIdx.x, lane = tid & 31, w = tid >> 5;
    int r = lane >> 2, c = lane & 3;
    int q0 = blockIdx.x * 128;
    int h = blockIdx.y, b = blockIdx.z;

    uint32_t ksBase = (uint32_t)__cvta_generic_to_shared(Ks);
    uint32_t psBase = (uint32_t)__cvta_generic_to_shared(Ps);

    int keyoff = ((lane >> 4) << 3) + (lane & 7);
    int dhalf  = ((lane >> 3) & 1) * 4;
    int prow   = ((lane >> 3) & 1) * 8 + (lane & 7);
    int pcol   = (lane >> 4) * 4;

    const float* qb = qkv + ((size_t)(b * Tt + q0 + w * 16)) * 3072 + h * 64;
    uint32_t qa[8][4];
    #pragma unroll
    for (int j = 0; j < 8; j++) {
        qa[j][0] = __float_as_uint(qb[(size_t)r * 3072 + j * 8 + c]);
        qa[j][1] = __float_as_uint(qb[(size_t)(r + 8) * 3072 + j * 8 + c]);
        qa[j][2] = __float_as_uint(qb[(size_t)r * 3072 + j * 8 + c + 4]);
        qa[j][3] = __float_as_uint(qb[(size_t)(r + 8) * 3072 + j * 8 + c + 4]);
    }

    float oacc[8][4];
    #pragma unroll
    for (int i = 0; i < 8; i++)
        #pragma unroll
        for (int k = 0; k < 4; k++) oacc[i][k] = 0.f;
    float m0 = -1e30f, m1 = -1e30f, l0 = 0.f, l1 = 0.f;
    int q_lo = q0 + w * 16 + r, q_hi = q_lo + 8;
    float* Pw = Ps + (w * 16) * PSS;
    uint32_t pwBase = psBase + (uint32_t)((w * 16) * PSS) * 4u;

    for (int k0 = 0; k0 < Tt; k0 += 64) {
        __syncthreads();
        #pragma unroll
        for (int i = 0; i < 4; i++) {
            int p = tid + i * 256;
            int kr = p >> 4, c4 = p & 15;
            const float* gk = qkv + ((size_t)(b * Tt + k0 + kr)) * 3072 + 1024 + h * 64 + c4 * 4;
            float4 kx = *(const float4*)gk;
            *(float4*)&Ks[kr * KSS + c4 * 4] = kx;
            float4 vx = *(const float4*)(gk + 1024);
            *(float4*)&Vs[kr * VSS + c4 * 4] = vx;
        }
        if (tid < 64) permS[tid] = perm[k0 + tid];
        __syncthreads();

        float sacc[8][4];
        #pragma unroll
        for (int i = 0; i < 8; i++)
            #pragma unroll
            for (int k = 0; k < 4; k++) sacc[i][k] = 0.f;
        #pragma unroll
        for (int j = 0; j < 8; j++) {
            #pragma unroll
            for (int np = 0; np < 4; np++) {
                uint32_t kb[4];
                ldsm_x4(kb, ksBase + (uint32_t)((np * 16 + keyoff) * KSS + j * 8 + dhalf) * 4u);
                mma_tf32(sacc[np * 2],     qa[j], kb);
                mma_tf32(sacc[np * 2 + 1], qa[j], kb + 2);
            }
        }

        float mx0 = -1e30f, mx1 = -1e30f;
        #pragma unroll
        for (int ni = 0; ni < 8; ni++) {
            int col = ni * 8 + 2 * c;
            int p0 = permS[col], p1 = permS[col + 1];
            sacc[ni][0] = (p0 > q_lo) ? -1e30f : sacc[ni][0] * 0.125f;
            sacc[ni][1] = (p1 > q_lo) ? -1e30f : sacc[ni][1] * 0.125f;
            sacc[ni][2] = (p0 > q_hi) ? -1e30f : sacc[ni][2] * 0.125f;
            sacc[ni][3] = (p1 > q_hi) ? -1e30f : sacc[ni][3] * 0.125f;
            mx0 = fmaxf(mx0, fmaxf(sacc[ni][0], sacc[ni][1]));
            mx1 = fmaxf(mx1, fmaxf(sacc[ni][2], sacc[ni][3]));
        }
        mx0 = fmaxf(mx0, __shfl_xor_sync(0xffffffffu, mx0, 1));
        mx0 = fmaxf(mx0, __shfl_xor_sync(0xffffffffu, mx0, 2));
        mx1 = fmaxf(mx1, __shfl_xor_sync(0xffffffffu, mx1, 1));
        mx1 = fmaxf(mx1, __shfl_xor_sync(0xffffffffu, mx1, 2));

        float nm0 = fmaxf(m0, mx0), nm1 = fmaxf(m1, mx1);
        float al0 = __expf(m0 - nm0), al1 = __expf(m1 - nm1);
        float ls0 = 0.f, ls1 = 0.f;
        #pragma unroll
        for (int ni = 0; ni < 8; ni++) {
            sacc[ni][0] = rna(__expf(sacc[ni][0] - nm0));
            sacc[ni][1] = rna(__expf(sacc[ni][1] - nm0));
            sacc[ni][2] = rna(__expf(sacc[ni][2] - nm1));
            sacc[ni][3] = rna(__expf(sacc[ni][3] - nm1));
            ls0 += sacc[ni][0] + sacc[ni][1];
            ls1 += sacc[ni][2] + sacc[ni][3];
        }
        ls0 += __shfl_xor_sync(0xffffffffu, ls0, 1);
        ls0 += __shfl_xor_sync(0xffffffffu, ls0, 2);
        ls1 += __shfl_xor_sync(0xffffffffu, ls1, 1);
        ls1 += __shfl_xor_sync(0xffffffffu, ls1, 2);
        l0 = l0 * al0 + ls0;
        l1 = l1 * al1 + ls1;
        m0 = nm0; m1 = nm1;
        #pragma unroll
        for (int ni = 0; ni < 8; ni++) {
            oacc[ni][0] *= al0; oacc[ni][1] *= al0;
            oacc[ni][2] *= al1; oacc[ni][3] *= al1;
        }

        #pragma unroll
        for (int ni = 0; ni < 8; ni++) {
            int col = ni * 8 + 2 * c;
            *(float2*)&Pw[r * PSS + col]       = make_float2(sacc[ni][0], sacc[ni][1]);
            *(float2*)&Pw[(r + 8) * PSS + col] = make_float2(sacc[ni][2], sacc[ni][3]);
        }
        __syncwarp();

        #pragma unroll
        for (int j = 0; j < 8; j++) {
            uint32_t pa[4];
            ldsm_x4(pa, pwBase + (uint32_t)(prow * PSS + j * 8 + pcol) * 4u);
            #pragma unroll
            for (int ni = 0; ni < 8; ni++) {
                uint32_t vb[2];
                vb[0] = __float_as_uint(Vs[(j * 8 + c) * VSS + ni * 8 + r]);
                vb[1] = __float_as_uint(Vs[(j * 8 + c + 4) * VSS + ni * 8 + r]);
                mma_tf32(oacc[ni], pa, vb);
            }
        }
    }

    float inv0 = 1.0f / l0, inv1 = 1.0f / l1;
    float* ob = out + ((size_t)(b * Tt + q_lo)) * 1024 + h * 64;
    #pragma unroll
    for (int ni = 0; ni < 8; ni++) {
        int col = ni * 8 + 2 * c;
        *(float2*)&ob[col] = make_float2(rna(oacc[ni][0] * inv0), rna(oacc[ni][1] * inv0));
        *(float2*)&ob[(size_t)8 * 1024 + col] =
            make_float2(rna(oacc[ni][2] * inv1), rna(oacc[ni][3] * inv1));
    }
}

// ---------------------------------------------------------------------------
// Launch
// ---------------------------------------------------------------------------
extern "C" void kernel_launch(void* const* d_in, const int* in_sizes, int n_in,
                              void* d_out, int out_size) {
    (void)in_sizes; (void)n_in; (void)out_size;
    const float* x     = (const float*)d_in[0];
    const int*   perm  = (const int*)d_in[1];
    const float* Wqkv  = (const float*)d_in[2];
    const float* Wproj = (const float*)d_in[3];
    const float* bproj = (const float*)d_in[4];
    const float* ln1_g = (const float*)d_in[5];
    const float* ln1_b = (const float*)d_in[6];
    const float* ln2_g = (const float*)d_in[7];
    const float* ln2_b = (const float*)d_in[8];
    const float* Wff1  = (const float*)d_in[9];
    const float* bff1  = (const float*)d_in[10];
    const float* Wff2  = (const float*)d_in[11];
    const float* bff2  = (const float*)d_in[12];
    float* out = (float*)d_out;

    void *ph, *pqkv, *patt, *px2, *pff, *pwq, *pwp, *pw1, *pw2;
    cudaGetSymbolAddress(&ph,   g_h);
    cudaGetSymbolAddress(&pqkv, g_qkv);
    cudaGetSymbolAddress(&patt, g_att);
    cudaGetSymbolAddress(&px2,  g_x2);
    cudaGetSymbolAddress(&pff,  g_ff);
    cudaGetSymbolAddress(&pwq,  g_wqkv);
    cudaGetSymbolAddress(&pwp,  g_wproj);
    cudaGetSymbolAddress(&pw1,  g_wff1);
    cudaGetSymbolAddress(&pw2,  g_wff2);
    float* h   = (float*)ph;
    float* qkv = (float*)pqkv;
    float* att = (float*)patt;
    float* x2  = (float*)px2;
    float* ff  = (float*)pff;
    float* wq  = (float*)pwq;
    float* wp  = (float*)pwp;
    float* w1  = (float*)pw1;
    float* w2  = (float*)pw2;

    cudaFuncSetAttribute((const void*)tgemm<0>,
                         cudaFuncAttributeMaxDynamicSharedMemorySize, GEMM_SMEM);
    cudaFuncSetAttribute((const void*)tgemm<1>,
                         cudaFuncAttributeMaxDynamicSharedMemorySize, GEMM_SMEM);
    cudaFuncSetAttribute((const void*)tgemm<2>,
                         cudaFuncAttributeMaxDynamicSharedMemorySize, GEMM_SMEM);
    cudaFuncSetAttribute((const void*)attn_mma,
                         cudaFuncAttributeMaxDynamicSharedMemorySize, ATTN_SMEM);

    // 0. Pre-round weights to tf32-exact fp32 (removes CVT from GEMM loops)
    {
        int n4;
        n4 = (Cc * 3 * Cc) / 4;  round_w_kernel<<<(n4 + 255) / 256, 256>>>(Wqkv,  wq, n4);
        n4 = (Cc * Cc) / 4;      round_w_kernel<<<(n4 + 255) / 256, 256>>>(Wproj, wp, n4);
        n4 = (Cc * FFf) / 4;     round_w_kernel<<<(n4 + 255) / 256, 256>>>(Wff1,  w1, n4);
        n4 = (FFf * Cc) / 4;     round_w_kernel<<<(n4 + 255) / 256, 256>>>(Wff2,  w2, n4);
    }

    // 1. h = LN1(x)                       (output tf32-rounded)
    ln_kernel<<<Mm, 256>>>(x, ln1_g, ln1_b, h);
    // 2. qkv = h @ Wqkv                   (output tf32-rounded)
    tgemm<0><<<dim3(3 * Cc / 128, Mm / 128), 256, GEMM_SMEM>>>(
        h, wq, nullptr, nullptr, qkv, Mm, 3 * Cc, Cc);
    // 3. attention -> att                 (output tf32-rounded)
    attn_mma<<<dim3(Tt / 128, Hh, Bb), 256, ATTN_SMEM>>>(qkv, perm, att);
    // 4. x2 = x + att @ Wproj + bproj     (full fp32 residual)
    tgemm<1><<<dim3(Cc / 128, Mm / 128), 256, GEMM_SMEM>>>(
        att, wp, bproj, x, x2, Mm, Cc, Cc);
    // 5. h = LN2(x2)                      (output tf32-rounded)
    ln_kernel<<<Mm, 256>>>(x2, ln2_g, ln2_b, h);
    // 6. ff = gelu(h @ Wff1 + bff1)       (output tf32-rounded)
    tgemm<2><<<dim3(FFf / 128, Mm / 128), 256, GEMM_SMEM>>>(
        h, w1, bff1, nullptr, ff, Mm, FFf, Cc);
    // 7. out = x2 + ff @ Wff2 + bff2      (full fp32 residual)
    tgemm<1><<<dim3(Cc / 128, Mm / 128), 256, GEMM_SMEM>>>(
        ff, w2, bff2, x2, out, Mm, Cc, FFf);
}

// round 10
// speedup vs baseline: 2.7808x; 1.5989x over previous
#include <cuda_runtime.h>
#include <cuda_fp16.h>
#include <math.h>
#include <stdint.h>

// Problem constants
constexpr int Bb = 4;
constexpr int Tt = 2048;
constexpr int Cc = 1024;
constexpr int Hh = 16;
constexpr int Dd = 64;
constexpr int FFf = 2048;
constexpr int Mm = Bb * Tt;   // 8192

// ---------------------------------------------------------------------------
// Scratch (device globals; no allocation allowed)
// ---------------------------------------------------------------------------
__device__ __half g_h   [(size_t)Mm * Cc];       // LN output (fp16)
__device__ __half g_qkv [(size_t)Mm * 3 * Cc];   // QKV (fp16)
__device__ __half g_att [(size_t)Mm * Cc];       // attention out (fp16)
__device__ float  g_x2  [(size_t)Mm * Cc];       // residual spine (fp32)
__device__ __half g_ff  [(size_t)Mm * FFf];      // gelu(ff1) (fp16)
// fp16, TRANSPOSED weights [N,K] (row-major N-rows of K halves)
__device__ __half g_wqkvT [(size_t)3 * Cc * Cc];
__device__ __half g_wprojT[(size_t)Cc * Cc];
__device__ __half g_wff1T [(size_t)FFf * Cc];
__device__ __half g_wff2T [(size_t)Cc * FFf];

// ---------------------------------------------------------------------------
// Helpers
// ---------------------------------------------------------------------------
__device__ __forceinline__ void mma_f16(float* c, const uint32_t* a,
                                        uint32_t b0, uint32_t b1) {
    asm volatile(
        "mma.sync.aligned.m16n8k16.row.col.f32.f16.f16.f32 "
        "{%0,%1,%2,%3}, {%4,%5,%6,%7}, {%8,%9}, {%0,%1,%2,%3};\n"
        : "+f"(c[0]), "+f"(c[1]), "+f"(c[2]), "+f"(c[3])
        : "r"(a[0]), "r"(a[1]), "r"(a[2]), "r"(a[3]), "r"(b0), "r"(b1));
}

__device__ __forceinline__ void cp16(uint32_t saddr, const void* g) {
    asm volatile("cp.async.cg.shared.global [%0], [%1], 16;\n" :: "r"(saddr), "l"(g));
}

__device__ __forceinline__ void ldsm_x4(uint32_t* r, uint32_t addr) {
    asm volatile("ldmatrix.sync.aligned.m8n8.x4.shared.b16 {%0,%1,%2,%3}, [%4];\n"
                 : "=r"(r[0]), "=r"(r[1]), "=r"(r[2]), "=r"(r[3]) : "r"(addr));
}
__device__ __forceinline__ void ldsm_x4_t(uint32_t* r, uint32_t addr) {
    asm volatile("ldmatrix.sync.aligned.m8n8.x4.trans.shared.b16 {%0,%1,%2,%3}, [%4];\n"
                 : "=r"(r[0]), "=r"(r[1]), "=r"(r[2]), "=r"(r[3]) : "r"(addr));
}

__device__ __forceinline__ uint32_t smem_u32(const void* p) {
    return (uint32_t)__cvta_generic_to_shared(p);
}

// ---------------------------------------------------------------------------
// Weight transpose + fp16 convert: src fp32 [K,N] -> dst fp16 [N,K]
// ---------------------------------------------------------------------------
__global__ void round_wT_kernel(const float* __restrict__ src,
                                __half* __restrict__ dst, int K, int N) {
    __shared__ float t[32][33];
    int nx = blockIdx.x * 32, ky = blockIdx.y * 32;
    #pragma unroll
    for (int i = 0; i < 4; i++) {
        int k = ky + threadIdx.y + i * 8;
        t[threadIdx.y + i * 8][threadIdx.x] = src[(size_t)k * N + nx + threadIdx.x];
    }
    __syncthreads();
    #pragma unroll
    for (int i = 0; i < 4; i++) {
        int n = nx + threadIdx.y + i * 8;
        dst[(size_t)n * K + ky + threadIdx.x] =
            __float2half_rn(t[threadIdx.x][threadIdx.y + i * 8]);
    }
}

// ---------------------------------------------------------------------------
// LayerNorm: fp32 in, fp16 out. One block per row, 256 threads.
// ---------------------------------------------------------------------------
__global__ void ln_kernel(const float* __restrict__ x,
                          const float* __restrict__ gamma,
                          const float* __restrict__ beta,
                          __half* __restrict__ out) {
    int row = blockIdx.x;
    int tid = threadIdx.x;
    const float4* xr = (const float4*)(x + (size_t)row * Cc);
    float4 v = xr[tid];

    float s  = v.x + v.y + v.z + v.w;
    float sq = v.x * v.x + v.y * v.y + v.z * v.z + v.w * v.w;
    #pragma unroll
    for (int o = 16; o > 0; o >>= 1) {
        s  += __shfl_xor_sync(0xffffffffu, s,  o);
        sq += __shfl_xor_sync(0xffffffffu, sq, o);
    }
    __shared__ float ss[8], ssq[8];
    __shared__ float mu_s, rs_s;
    int w = tid >> 5;
    if ((tid & 31) == 0) { ss[w] = s; ssq[w] = sq; }
    __syncthreads();
    if (tid == 0) {
        float S = 0.f, SQ = 0.f;
        #pragma unroll
        for (int i = 0; i < 8; i++) { S += ss[i]; SQ += ssq[i]; }
        float mu  = S * (1.0f / (float)Cc);
        float var = SQ * (1.0f / (float)Cc) - mu * mu;
        mu_s = mu;
        rs_s = rsqrtf(var + 1e-5f);
    }
    __syncthreads();
    float mu = mu_s, rs = rs_s;
    float4 gv = ((const float4*)gamma)[tid];
    float4 bv = ((const float4*)beta)[tid];
    __half2 h0 = __floats2half2_rn((v.x - mu) * rs * gv.x + bv.x,
                                   (v.y - mu) * rs * gv.y + bv.y);
    __half2 h1 = __floats2half2_rn((v.z - mu) * rs * gv.z + bv.z,
                                   (v.w - mu) * rs * gv.w + bv.w);
    __half2* op = (__half2*)(out + (size_t)row * Cc + tid * 4);
    op[0] = h0;
    op[1] = h1;
}

// ---------------------------------------------------------------------------
// fp16 tensor-core GEMM: C[M,N] = A[M,K] @ Bt[N,K]^T  (+bias/residual/gelu)
// BM=BN=128, BK=32, 256 threads = 8 warps (2x4 grid, 64x32 warp tiles).
// 3-stage cp.async. A- and B-frags via ldmatrix.x4 (B from [N,K] rows —
// layout matches fp16 col-major B-fragment exactly).
// EPI: 0 = fp16 out (qkv), 1 = +bias+residual fp32 out, 2 = +bias GELU fp16.
// ---------------------------------------------------------------------------
constexpr int GS = 40;                             // smem stride in halves (80B)
constexpr int TILE_H = 128 * GS;                   // halves per tile
constexpr int STAGE_B = 2 * TILE_H * 2;            // 20480 bytes (A+B)
constexpr int GEMM_SMEM = 3 * STAGE_B;             // 61440 bytes

template <int EPI>
__global__ __launch_bounds__(256, 2) void tgemm(
    const __half* __restrict__ A, const __half* __restrict__ Bt,
    const float* __restrict__ bias, const float* __restrict__ res,
    void* __restrict__ CoutV, int Mn, int Nn, int Kn) {
    extern __shared__ __half smem_g[];

    int tid = threadIdx.x, lane = tid & 31, w = tid >> 5;
    int wm = w >> 2, wn = w & 3;           // 2 x 4 warp grid
    int row0 = blockIdx.y * 128, col0 = blockIdx.x * 128;
    int r = lane >> 2, c = lane & 3;

    float acc[4][4][4];
    #pragma unroll
    for (int i = 0; i < 4; i++)
        #pragma unroll
        for (int j = 0; j < 4; j++)
            #pragma unroll
            for (int k = 0; k < 4; k++) acc[i][j][k] = 0.f;

    uint32_t sb = smem_u32(smem_g);

    // ldmatrix lane geometry (shared by A and B frags)
    int frow = ((lane >> 3) & 1) * 8 + (lane & 7);      // 0..15
    int fcol = (lane >> 4) * 8;                         // 0 or 8 (halves)
    uint32_t laneOff = (uint32_t)(frow * GS + fcol) * 2u;

    auto loadT = [&](int st, int kt, const __half* src, int which) {
        // tile: 128 rows x 32 halves; 4 cp16 per row; 512 chunks, 2 iters
        uint32_t base = sb + (uint32_t)(st * STAGE_B + which * TILE_H * 2);
        int k0 = kt * 32;
        #pragma unroll
        for (int i = 0; i < 2; i++) {
            int ch = tid + i * 256;
            int rr = ch >> 2, c8 = ch & 3;
            cp16(base + (uint32_t)(rr * GS + c8 * 8) * 2u,
                 src + (size_t)rr * Kn + k0 + c8 * 8);
        }
    };

    const __half* Ap = A + (size_t)row0 * Kn;
    const __half* Bp = Bt + (size_t)col0 * Kn;

    int nk = Kn >> 5;
    loadT(0, 0, Ap, 0); loadT(0, 0, Bp, 1);
    asm volatile("cp.async.commit_group;\n" ::: "memory");
    loadT(1, 1, Ap, 0); loadT(1, 1, Bp, 1);
    asm volatile("cp.async.commit_group;\n" ::: "memory");

    for (int kt = 0; kt < nk; kt++) {
        int st = kt % 3;
        asm volatile("cp.async.wait_group 1;\n" ::: "memory");
        __syncthreads();
        if (kt + 2 < nk) {
            int st2 = (kt + 2) % 3;
            loadT(st2, kt + 2, Ap, 0); loadT(st2, kt + 2, Bp, 1);
        }
        asm volatile("cp.async.commit_group;\n" ::: "memory");

        uint32_t aStage = sb + (uint32_t)(st * STAGE_B) + laneOff;
        uint32_t bStage = aStage + (uint32_t)(TILE_H * 2);
        #pragma unroll
        for (int kk = 0; kk < 2; kk++) {             // 2 x k16 per stage
            int kh = kk * 16;
            uint32_t af[4][4], bfr[2][4];
            #pragma unroll
            for (int mi = 0; mi < 4; mi++)
                ldsm_x4(af[mi], aStage + (uint32_t)((wm * 64 + mi * 16) * GS + kh) * 2u);
            #pragma unroll
            for (int g = 0; g < 2; g++)
                ldsm_x4(bfr[g], bStage + (uint32_t)((wn * 32 + g * 16) * GS + kh) * 2u);
            #pragma unroll
            for (int mi = 0; mi < 4; mi++)
                #pragma unroll
                for (int ni = 0; ni < 4; ni++) {
                    int g = ni >> 1, p = ni & 1;
                    mma_f16(acc[mi][ni], af[mi], bfr[g][0 + p], bfr[g][2 + p]);
                }
        }
        __syncthreads();
    }

    // Epilogue: C fragment rows r/r+8, cols 2c/2c+1
    #pragma unroll
    for (int mi = 0; mi < 4; mi++) {
        int rr0 = row0 + wm * 64 + mi * 16 + r;
        #pragma unroll
        for (int ni = 0; ni < 4; ni++) {
            int cc = col0 + wn * 32 + ni * 8 + 2 * c;
            float v0 = acc[mi][ni][0], v1 = acc[mi][ni][1];
            float v2 = acc[mi][ni][2], v3 = acc[mi][ni][3];
            if constexpr (EPI == 0) {
                __half* Cout = (__half*)CoutV;
                *(__half2*)&Cout[(size_t)rr0 * Nn + cc]       = __floats2half2_rn(v0, v1);
                *(__half2*)&Cout[(size_t)(rr0 + 8) * Nn + cc] = __floats2half2_rn(v2, v3);
            } else if constexpr (EPI == 1) {
                float* Cout = (float*)CoutV;
                float b0 = bias[cc], b1 = bias[cc + 1];
                float2 r0 = *(const float2*)&res[(size_t)rr0 * Nn + cc];
                float2 r1 = *(const float2*)&res[(size_t)(rr0 + 8) * Nn + cc];
                *(float2*)&Cout[(size_t)rr0 * Nn + cc] =
                    make_float2(v0 + b0 + r0.x, v1 + b1 + r0.y);
                *(float2*)&Cout[(size_t)(rr0 + 8) * Nn + cc] =
                    make_float2(v2 + b0 + r1.x, v3 + b1 + r1.y);
            } else {
                __half* Cout = (__half*)CoutV;
                float b0 = bias[cc], b1 = bias[cc + 1];
                v0 += b0; v1 += b1; v2 += b0; v3 += b1;
                v0 = 0.5f * v0 * (1.0f + erff(v0 * 0.70710678118654752f));
                v1 = 0.5f * v1 * (1.0f + erff(v1 * 0.70710678118654752f));
                v2 = 0.5f * v2 * (1.0f + erff(v2 * 0.70710678118654752f));
                v3 = 0.5f * v3 * (1.0f + erff(v3 * 0.70710678118654752f));
                *(__half2*)&Cout[(size_t)rr0 * Nn + cc]       = __floats2half2_rn(v0, v1);
                *(__half2*)&Cout[(size_t)(rr0 + 8) * Nn + cc] = __floats2half2_rn(v2, v3);
            }
        }
    }
}

// ---------------------------------------------------------------------------
// fp16 tensor-core flash attention with permutation mask.
// 128 queries/block (8 warps x 16 rows), KV tiles of 64, D=64.
// Q in registers (fp16 A-frags); K/P-frags via ldmatrix.x4; V via
// ldmatrix.x4.trans. Softmax in fp32 on fragments.
// ---------------------------------------------------------------------------
constexpr int KSH = 72;              // halves (144B stride: 9x16B, conflict-free)
constexpr int KS_H = 64 * KSH;
constexpr int VS_H = 64 * KSH;
constexpr int PS_H = 128 * KSH;
constexpr int ATTN_SMEM = (KS_H + VS_H + PS_H) * 2 + 64 * 4;  // 37120 B

__global__ __launch_bounds__(256, 2) void attn_mma(
    const __half* __restrict__ qkv, const int* __restrict__ perm,
    __half* __restrict__ out) {
    extern __shared__ __half smem_a[];
    __half* Ks = smem_a;
    __half* Vs = Ks + KS_H;
    __half* Ps = Vs + VS_H;
    int*    permS = (int*)(Ps + PS_H);

    int tid = threadIdx.x, lane = tid & 31, w = tid >> 5;
    int r = lane >> 2, c = lane & 3;
    int q0 = blockIdx.x * 128;
    int h = blockIdx.y, b = blockIdx.z;

    uint32_t ksBase = smem_u32(Ks);
    uint32_t vsBase = smem_u32(Vs);
    uint32_t psBase = smem_u32(Ps);

    int frow = ((lane >> 3) & 1) * 8 + (lane & 7);   // 0..15
    int fcol = (lane >> 4) * 8;                      // 0/8 halves

    // Q fragments (fp16): 4 k16 chunks, 4 regs each
    const __half* qb = qkv + ((size_t)(b * Tt + q0 + w * 16)) * 3072 + h * 64;
    uint32_t qa[4][4];
    #pragma unroll
    for (int j = 0; j < 4; j++) {
        qa[j][0] = *(const uint32_t*)&qb[(size_t)r * 3072 + j * 16 + 2 * c];
        qa[j][1] = *(const uint32_t*)&qb[(size_t)(r + 8) * 3072 + j * 16 + 2 * c];
        qa[j][2] = *(const uint32_t*)&qb[(size_t)r * 3072 + j * 16 + 8 + 2 * c];
        qa[j][3] = *(const uint32_t*)&qb[(size_t)(r + 8) * 3072 + j * 16 + 8 + 2 * c];
    }

    float oacc[8][4];
    #pragma unroll
    for (int i = 0; i < 8; i++)
        #pragma unroll
        for (int k = 0; k < 4; k++) oacc[i][k] = 0.f;
    float m0 = -1e30f, m1 = -1e30f, l0 = 0.f, l1 = 0.f;
    int q_lo = q0 + w * 16 + r, q_hi = q_lo + 8;
    __half* Pw = Ps + (w * 16) * KSH;
    uint32_t pwBase = psBase + (uint32_t)((w * 16) * KSH) * 2u;

    for (int k0 = 0; k0 < Tt; k0 += 64) {
        __syncthreads();
        // K/V tiles: 64 rows x 64 halves = 8 chunks/row
        #pragma unroll
        for (int i = 0; i < 2; i++) {
            int p = tid + i * 256;
            int kr = p >> 3, c8 = p & 7;
            const __half* gk = qkv + ((size_t)(b * Tt + k0 + kr)) * 3072 + 1024
                             + h * 64 + c8 * 8;
            *(uint4*)&Ks[kr * KSH + c8 * 8] = *(const uint4*)gk;
            *(uint4*)&Vs[kr * KSH + c8 * 8] = *(const uint4*)(gk + 1024);
        }
        if (tid < 64) permS[tid] = perm[k0 + tid];
        __syncthreads();

        // S = Q @ K^T : 4 k16 chunks x 4 key16 blocks
        float sacc[8][4];
        #pragma unroll
        for (int i = 0; i < 8; i++)
            #pragma unroll
            for (int k = 0; k < 4; k++) sacc[i][k] = 0.f;
        #pragma unroll
        for (int j = 0; j < 4; j++) {
            #pragma unroll
            for (int np = 0; np < 4; np++) {
                uint32_t kb[4];
                ldsm_x4(kb, ksBase
                        + (uint32_t)((np * 16 + frow) * KSH + j * 16 + fcol) * 2u);
                mma_f16(sacc[np * 2],     qa[j], kb[0], kb[2]);
                mma_f16(sacc[np * 2 + 1], qa[j], kb[1], kb[3]);
            }
        }

        // Mask + scale + per-row max
        float mx0 = -1e30f, mx1 = -1e30f;
        #pragma unroll
        for (int ni = 0; ni < 8; ni++) {
            int col = ni * 8 + 2 * c;
            int p0 = permS[col], p1 = permS[col + 1];
            sacc[ni][0] = (p0 > q_lo) ? -1e30f : sacc[ni][0] * 0.125f;
            sacc[ni][1] = (p1 > q_lo) ? -1e30f : sacc[ni][1] * 0.125f;
            sacc[ni][2] = (p0 > q_hi) ? -1e30f : sacc[ni][2] * 0.125f;
            sacc[ni][3] = (p1 > q_hi) ? -1e30f : sacc[ni][3] * 0.125f;
            mx0 = fmaxf(mx0, fmaxf(sacc[ni][0], sacc[ni][1]));
            mx1 = fmaxf(mx1, fmaxf(sacc[ni][2], sacc[ni][3]));
        }
        mx0 = fmaxf(mx0, __shfl_xor_sync(0xffffffffu, mx0, 1));
        mx0 = fmaxf(mx0, __shfl_xor_sync(0xffffffffu, mx0, 2));
        mx1 = fmaxf(mx1, __shfl_xor_sync(0xffffffffu, mx1, 1));
        mx1 = fmaxf(mx1, __shfl_xor_sync(0xffffffffu, mx1, 2));

        float nm0 = fmaxf(m0, mx0), nm1 = fmaxf(m1, mx1);
        float al0 = __expf(m0 - nm0), al1 = __expf(m1 - nm1);
        float ls0 = 0.f, ls1 = 0.f;
        #pragma unroll
        for (int ni = 0; ni < 8; ni++) {
            sacc[ni][0] = __expf(sacc[ni][0] - nm0);
            sacc[ni][1] = __expf(sacc[ni][1] - nm0);
            sacc[ni][2] = __expf(sacc[ni][2] - nm1);
            sacc[ni][3] = __expf(sacc[ni][3] - nm1);
            ls0 += sacc[ni][0] + sacc[ni][1];
            ls1 += sacc[ni][2] + sacc[ni][3];
        }
        ls0 += __shfl_xor_sync(0xffffffffu, ls0, 1);
        ls0 += __shfl_xor_sync(0xffffffffu, ls0, 2);
        ls1 += __shfl_xor_sync(0xffffffffu, ls1, 1);
        ls1 += __shfl_xor_sync(0xffffffffu, ls1, 2);
        l0 = l0 * al0 + ls0;
        l1 = l1 * al1 + ls1;
        m0 = nm0; m1 = nm1;
        #pragma unroll
        for (int ni = 0; ni < 8; ni++) {
            oacc[ni][0] *= al0; oacc[ni][1] *= al0;
            oacc[ni][2] *= al1; oacc[ni][3] *= al1;
        }

        // P (fp16) to per-warp smem in C-frag layout
        #pragma unroll
        for (int ni = 0; ni < 8; ni++) {
            int col = ni * 8 + 2 * c;
            *(__half2*)&Pw[r * KSH + col]       = __floats2half2_rn(sacc[ni][0], sacc[ni][1]);
            *(__half2*)&Pw[(r + 8) * KSH + col] = __floats2half2_rn(sacc[ni][2], sacc[ni][3]);
        }
        __syncwarp();

        // O += P @ V : 4 key16 chunks; V-frags via ldmatrix.trans
        #pragma unroll
        for (int j = 0; j < 4; j++) {
            uint32_t pa[4];
            ldsm_x4(pa, pwBase + (uint32_t)(frow * KSH + j * 16 + fcol) * 2u);
            #pragma unroll
            for (int db = 0; db < 4; db++) {
                uint32_t vb[4];
                ldsm_x4_t(vb, vsBase
                          + (uint32_t)((j * 16 + frow) * KSH + db * 16 + fcol) * 2u);
                mma_f16(oacc[db * 2],     pa, vb[0], vb[1]);
                mma_f16(oacc[db * 2 + 1], pa, vb[2], vb[3]);
            }
        }
    }

    float inv0 = 1.0f / l0, inv1 = 1.0f / l1;
    __half* ob = out + ((size_t)(b * Tt + q_lo)) * 1024 + h * 64;
    #pragma unroll
    for (int ni = 0; ni < 8; ni++) {
        int col = ni * 8 + 2 * c;
        *(__half2*)&ob[col] = __floats2half2_rn(oacc[ni][0] * inv0, oacc[ni][1] * inv0);
        *(__half2*)&ob[(size_t)8 * 1024 + col] =
            __floats2half2_rn(oacc[ni][2] * inv1, oacc[ni][3] * inv1);
    }
}

// ---------------------------------------------------------------------------
// Launch
// ---------------------------------------------------------------------------
extern "C" void kernel_launch(void* const* d_in, const int* in_sizes, int n_in,
                              void* d_out, int out_size) {
    (void)in_sizes; (void)n_in; (void)out_size;
    const float* x     = (const float*)d_in[0];
    const int*   perm  = (const int*)d_in[1];
    const float* Wqkv  = (const float*)d_in[2];
    const float* Wproj = (const float*)d_in[3];
    const float* bproj = (const float*)d_in[4];
    const float* ln1_g = (const float*)d_in[5];
    const float* ln1_b = (const float*)d_in[6];
    const float* ln2_g = (const float*)d_in[7];
    const float* ln2_b = (const float*)d_in[8];
    const float* Wff1  = (const float*)d_in[9];
    const float* bff1  = (const float*)d_in[10];
    const float* Wff2  = (const float*)d_in[11];
    const float* bff2  = (const float*)d_in[12];
    float* out = (float*)d_out;

    void *ph, *pqkv, *patt, *px2, *pff, *pwq, *pwp, *pw1, *pw2;
    cudaGetSymbolAddress(&ph,   g_h);
    cudaGetSymbolAddress(&pqkv, g_qkv);
    cudaGetSymbolAddress(&patt, g_att);
    cudaGetSymbolAddress(&px2,  g_x2);
    cudaGetSymbolAddress(&pff,  g_ff);
    cudaGetSymbolAddress(&pwq,  g_wqkvT);
    cudaGetSymbolAddress(&pwp,  g_wprojT);
    cudaGetSymbolAddress(&pw1,  g_wff1T);
    cudaGetSymbolAddress(&pw2,  g_wff2T);
    __half* h   = (__half*)ph;
    __half* qkv = (__half*)pqkv;
    __half* att = (__half*)patt;
    float*  x2  = (float*)px2;
    __half* ff  = (__half*)pff;
    __half* wqT = (__half*)pwq;
    __half* wpT = (__half*)pwp;
    __half* w1T = (__half*)pw1;
    __half* w2T = (__half*)pw2;

    cudaFuncSetAttribute((const void*)tgemm<0>,
                         cudaFuncAttributeMaxDynamicSharedMemorySize, GEMM_SMEM);
    cudaFuncSetAttribute((const void*)tgemm<1>,
                         cudaFuncAttributeMaxDynamicSharedMemorySize, GEMM_SMEM);
    cudaFuncSetAttribute((const void*)tgemm<2>,
                         cudaFuncAttributeMaxDynamicSharedMemorySize, GEMM_SMEM);
    cudaFuncSetAttribute((const void*)attn_mma,
                         cudaFuncAttributeMaxDynamicSharedMemorySize, ATTN_SMEM);

    // 0. Weight transpose + fp16 convert: W[K,N] -> Wt[N,K]
    {
        dim3 blk(32, 8);
        round_wT_kernel<<<dim3(3 * Cc / 32, Cc / 32), blk>>>(Wqkv,  wqT, Cc,  3 * Cc);
        round_wT_kernel<<<dim3(Cc / 32, Cc / 32),     blk>>>(Wproj, wpT, Cc,  Cc);
        round_wT_kernel<<<dim3(FFf / 32, Cc / 32),    blk>>>(Wff1,  w1T, Cc,  FFf);
        round_wT_kernel<<<dim3(Cc / 32, FFf / 32),    blk>>>(Wff2,  w2T, FFf, Cc);
    }

    // 1. h = LN1(x)                        (fp16 out)
    ln_kernel<<<Mm, 256>>>(x, ln1_g, ln1_b, h);
    // 2. qkv = h @ Wqkv                    (fp16 out)
    tgemm<0><<<dim3(3 * Cc / 128, Mm / 128), 256, GEMM_SMEM>>>(
        h, wqT, nullptr, nullptr, qkv, Mm, 3 * Cc, Cc);
    // 3. attention -> att                  (fp16 out)
    attn_mma<<<dim3(Tt / 128, Hh, Bb), 256, ATTN_SMEM>>>(qkv, perm, att);
    // 4. x2 = x + att @ Wproj + bproj      (fp32 residual spine)
    tgemm<1><<<dim3(Cc / 128, Mm / 128), 256, GEMM_SMEM>>>(
        att, wpT, bproj, x, x2, Mm, Cc, Cc);
    // 5. h = LN2(x2)                       (fp16 out)
    ln_kernel<<<Mm, 256>>>(x2, ln2_g, ln2_b, h);
    // 6. ff = gelu(h @ Wff1 + bff1)        (fp16 out)
    tgemm<2><<<dim3(FFf / 128, Mm / 128), 256, GEMM_SMEM>>>(
        h, w1T, bff1, nullptr, ff, Mm, FFf, Cc);
    // 7. out = x2 + ff @ Wff2 + bff2       (fp32 out)
    tgemm<1><<<dim3(Cc / 128, Mm / 128), 256, GEMM_SMEM>>>(
        ff, w2T, bff2, x2, out, Mm, Cc, FFf);
}

// round 13
// speedup vs baseline: 2.9492x; 1.0606x over previous
#include <cuda_runtime.h>
#include <cuda_fp16.h>
#include <math.h>
#include <stdint.h>

// Problem constants
constexpr int Bb = 4;
constexpr int Tt = 2048;
constexpr int Cc = 1024;
constexpr int Hh = 16;
constexpr int Dd = 64;
constexpr int FFf = 2048;
constexpr int Mm = Bb * Tt;   // 8192

// ---------------------------------------------------------------------------
// Scratch (device globals; no allocation allowed)
// ---------------------------------------------------------------------------
__device__ __half g_h   [(size_t)Mm * Cc];
__device__ __half g_qkv [(size_t)Mm * 3 * Cc];
__device__ __half g_att [(size_t)Mm * Cc];
__device__ float  g_x2  [(size_t)Mm * Cc];
__device__ __half g_ff  [(size_t)Mm * FFf];
__device__ __half g_wqkvT [(size_t)3 * Cc * Cc];
__device__ __half g_wprojT[(size_t)Cc * Cc];
__device__ __half g_wff1T [(size_t)FFf * Cc];
__device__ __half g_wff2T [(size_t)Cc * FFf];

// ---------------------------------------------------------------------------
// Helpers
// ---------------------------------------------------------------------------
__device__ __forceinline__ void mma_f16(float* c, const uint32_t* a,
                                        uint32_t b0, uint32_t b1) {
    asm volatile(
        "mma.sync.aligned.m16n8k16.row.col.f32.f16.f16.f32 "
        "{%0,%1,%2,%3}, {%4,%5,%6,%7}, {%8,%9}, {%0,%1,%2,%3};\n"
        : "+f"(c[0]), "+f"(c[1]), "+f"(c[2]), "+f"(c[3])
        : "r"(a[0]), "r"(a[1]), "r"(a[2]), "r"(a[3]), "r"(b0), "r"(b1));
}

__device__ __forceinline__ void cp16(uint32_t saddr, const void* g) {
    asm volatile("cp.async.cg.shared.global [%0], [%1], 16;\n" :: "r"(saddr), "l"(g));
}

__device__ __forceinline__ void ldsm_x4(uint32_t* r, uint32_t addr) {
    asm volatile("ldmatrix.sync.aligned.m8n8.x4.shared.b16 {%0,%1,%2,%3}, [%4];\n"
                 : "=r"(r[0]), "=r"(r[1]), "=r"(r[2]), "=r"(r[3]) : "r"(addr));
}
__device__ __forceinline__ void ldsm_x4_t(uint32_t* r, uint32_t addr) {
    asm volatile("ldmatrix.sync.aligned.m8n8.x4.trans.shared.b16 {%0,%1,%2,%3}, [%4];\n"
                 : "=r"(r[0]), "=r"(r[1]), "=r"(r[2]), "=r"(r[3]) : "r"(addr));
}

__device__ __forceinline__ uint32_t smem_u32(const void* p) {
    return (uint32_t)__cvta_generic_to_shared(p);
}

// ---------------------------------------------------------------------------
// Weight transpose + fp16 convert: src fp32 [K,N] -> dst fp16 [N,K]
// ---------------------------------------------------------------------------
__global__ void round_wT_kernel(const float* __restrict__ src,
                                __half* __restrict__ dst, int K, int N) {
    __shared__ float t[32][33];
    int nx = blockIdx.x * 32, ky = blockIdx.y * 32;
    #pragma unroll
    for (int i = 0; i < 4; i++) {
        int k = ky + threadIdx.y + i * 8;
        t[threadIdx.y + i * 8][threadIdx.x] = src[(size_t)k * N + nx + threadIdx.x];
    }
    __syncthreads();
    #pragma unroll
    for (int i = 0; i < 4; i++) {
        int n = nx + threadIdx.y + i * 8;
        dst[(size_t)n * K + ky + threadIdx.x] =
            __float2half_rn(t[threadIdx.x][threadIdx.y + i * 8]);
    }
}

// ---------------------------------------------------------------------------
// LayerNorm: fp32 in, fp16 out. One block per row, 256 threads.
// ---------------------------------------------------------------------------
__global__ void ln_kernel(const float* __restrict__ x,
                          const float* __restrict__ gamma,
                          const float* __restrict__ beta,
                          __half* __restrict__ out) {
    int row = blockIdx.x;
    int tid = threadIdx.x;
    const float4* xr = (const float4*)(x + (size_t)row * Cc);
    float4 v = xr[tid];

    float s  = v.x + v.y + v.z + v.w;
    float sq = v.x * v.x + v.y * v.y + v.z * v.z + v.w * v.w;
    #pragma unroll
    for (int o = 16; o > 0; o >>= 1) {
        s  += __shfl_xor_sync(0xffffffffu, s,  o);
        sq += __shfl_xor_sync(0xffffffffu, sq, o);
    }
    __shared__ float ss[8], ssq[8];
    __shared__ float mu_s, rs_s;
    int w = tid >> 5;
    if ((tid & 31) == 0) { ss[w] = s; ssq[w] = sq; }
    __syncthreads();
    if (tid == 0) {
        float S = 0.f, SQ = 0.f;
        #pragma unroll
        for (int i = 0; i < 8; i++) { S += ss[i]; SQ += ssq[i]; }
        float mu  = S * (1.0f / (float)Cc);
        float var = SQ * (1.0f / (float)Cc) - mu * mu;
        mu_s = mu;
        rs_s = rsqrtf(var + 1e-5f);
    }
    __syncthreads();
    float mu = mu_s, rs = rs_s;
    float4 gv = ((const float4*)gamma)[tid];
    float4 bv = ((const float4*)beta)[tid];
    __half2 h0 = __floats2half2_rn((v.x - mu) * rs * gv.x + bv.x,
                                   (v.y - mu) * rs * gv.y + bv.y);
    __half2 h1 = __floats2half2_rn((v.z - mu) * rs * gv.z + bv.z,
                                   (v.w - mu) * rs * gv.w + bv.w);
    __half2* op = (__half2*)(out + (size_t)row * Cc + tid * 4);
    op[0] = h0;
    op[1] = h1;
}

// ---------------------------------------------------------------------------
// fp16 tensor-core GEMM: C[M,N] = A[M,K] @ Bt[N,K]^T  (+bias/residual/gelu)
// BM=BN=128, BK=64, 256 threads = 8 warps (2x4 grid, 64x32 warp tiles).
// 3-stage cp.async (prefetch distance 128 K), one barrier per 128 mma.
// 2 CTAs/SM (2 x 110.6KB + reserve <= 228KB carveout).
// EPI: 0 = fp16 out (qkv), 1 = +bias+residual fp32 out, 2 = +bias GELU fp16.
// ---------------------------------------------------------------------------
constexpr int GS = 72;                              // smem stride halves (144B)
constexpr int TILE_B = 128 * GS * 2;                // 18432 bytes per tile
constexpr int STAGE_B = 2 * TILE_B;                 // 36864 bytes (A+B)
constexpr int GEMM_SMEM = 3 * STAGE_B;              // 110592 bytes

template <int EPI>
__global__ __launch_bounds__(256, 2) void tgemm(
    const __half* __restrict__ A, const __half* __restrict__ Bt,
    const float* __restrict__ bias, const float* __restrict__ res,
    void* __restrict__ CoutV, int Mn, int Nn, int Kn) {
    extern __shared__ __half smem_g[];

    int tid = threadIdx.x, lane = tid & 31, w = tid >> 5;
    int wm = w >> 2, wn = w & 3;
    int row0 = blockIdx.y * 128, col0 = blockIdx.x * 128;
    int r = lane >> 2, c = lane & 3;

    float acc[4][4][4];
    #pragma unroll
    for (int i = 0; i < 4; i++)
        #pragma unroll
        for (int j = 0; j < 4; j++)
            #pragma unroll
            for (int k = 0; k < 4; k++) acc[i][j][k] = 0.f;

    uint32_t sb = smem_u32(smem_g);

    int frow = ((lane >> 3) & 1) * 8 + (lane & 7);
    int fcol = (lane >> 4) * 8;
    uint32_t laneOff = (uint32_t)(frow * GS + fcol) * 2u;

    const __half* Ap = A + (size_t)row0 * Kn;
    const __half* Bp = Bt + (size_t)col0 * Kn;

    // tile: 128 rows x 64 halves = 8 cp16/row; A then B = 2048 chunks, 8/thread
    auto loadT = [&](int st, int kt) {
        int k0 = kt * 64;
        uint32_t base = sb + (uint32_t)(st * STAGE_B);
        #pragma unroll
        for (int i = 0; i < 8; i++) {
            int ch = tid + i * 256;
            int which = ch >> 10;          // 0 = A, 1 = B
            int idx = ch & 1023;
            int rr = idx >> 3, c8 = idx & 7;
            const __half* src = which ? Bp : Ap;
            cp16(base + (uint32_t)(which * TILE_B) + (uint32_t)(rr * GS + c8 * 8) * 2u,
                 src + (size_t)rr * Kn + k0 + c8 * 8);
        }
    };

    int nk = Kn >> 6;
    loadT(0, 0);
    asm volatile("cp.async.commit_group;\n" ::: "memory");
    loadT(1, 1);
    asm volatile("cp.async.commit_group;\n" ::: "memory");

    for (int kt = 0; kt < nk; kt++) {
        int st = kt % 3;
        asm volatile("cp.async.wait_group 1;\n" ::: "memory");
        __syncthreads();
        if (kt + 2 < nk) loadT((kt + 2) % 3, kt + 2);
        asm volatile("cp.async.commit_group;\n" ::: "memory");

        uint32_t aStage = sb + (uint32_t)(st * STAGE_B) + laneOff;
        uint32_t bStage = aStage + (uint32_t)TILE_B;
        #pragma unroll
        for (int kk = 0; kk < 4; kk++) {             // 4 x k16 per stage
            int kh = kk * 16;
            uint32_t af[4][4], bfr[2][4];
            #pragma unroll
            for (int mi = 0; mi < 4; mi++)
                ldsm_x4(af[mi], aStage + (uint32_t)((wm * 64 + mi * 16) * GS + kh) * 2u);
            #pragma unroll
            for (int g = 0; g < 2; g++)
                ldsm_x4(bfr[g], bStage + (uint32_t)((wn * 32 + g * 16) * GS + kh) * 2u);
            #pragma unroll
            for (int mi = 0; mi < 4; mi++)
                #pragma unroll
                for (int ni = 0; ni < 4; ni++) {
                    int g = ni >> 1, p = ni & 1;
                    mma_f16(acc[mi][ni], af[mi], bfr[g][0 + p], bfr[g][2 + p]);
                }
        }
        __syncthreads();
    }

    #pragma unroll
    for (int mi = 0; mi < 4; mi++) {
        int rr0 = row0 + wm * 64 + mi * 16 + r;
        #pragma unroll
        for (int ni = 0; ni < 4; ni++) {
            int cc = col0 + wn * 32 + ni * 8 + 2 * c;
            float v0 = acc[mi][ni][0], v1 = acc[mi][ni][1];
            float v2 = acc[mi][ni][2], v3 = acc[mi][ni][3];
            if constexpr (EPI == 0) {
                __half* Cout = (__half*)CoutV;
                *(__half2*)&Cout[(size_t)rr0 * Nn + cc]       = __floats2half2_rn(v0, v1);
                *(__half2*)&Cout[(size_t)(rr0 + 8) * Nn + cc] = __floats2half2_rn(v2, v3);
            } else if constexpr (EPI == 1) {
                float* Cout = (float*)CoutV;
                float b0 = bias[cc], b1 = bias[cc + 1];
                float2 r0 = *(const float2*)&res[(size_t)rr0 * Nn + cc];
                float2 r1 = *(const float2*)&res[(size_t)(rr0 + 8) * Nn + cc];
                *(float2*)&Cout[(size_t)rr0 * Nn + cc] =
                    make_float2(v0 + b0 + r0.x, v1 + b1 + r0.y);
                *(float2*)&Cout[(size_t)(rr0 + 8) * Nn + cc] =
                    make_float2(v2 + b0 + r1.x, v3 + b1 + r1.y);
            } else {
                __half* Cout = (__half*)CoutV;
                float b0 = bias[cc], b1 = bias[cc + 1];
                v0 += b0; v1 += b1; v2 += b0; v3 += b1;
                v0 = 0.5f * v0 * (1.0f + erff(v0 * 0.70710678118654752f));
                v1 = 0.5f * v1 * (1.0f + erff(v1 * 0.70710678118654752f));
                v2 = 0.5f * v2 * (1.0f + erff(v2 * 0.70710678118654752f));
                v3 = 0.5f * v3 * (1.0f + erff(v3 * 0.70710678118654752f));
                *(__half2*)&Cout[(size_t)rr0 * Nn + cc]       = __floats2half2_rn(v0, v1);
                *(__half2*)&Cout[(size_t)(rr0 + 8) * Nn + cc] = __floats2half2_rn(v2, v3);
            }
        }
    }
}

// ---------------------------------------------------------------------------
// fp16 flash attention with permutation mask.
// 128 queries/block (8 warps x 16 rows), KV tiles of 64, D=64.
// K/V through a 3-stage cp.async ring (prefetch 2 tiles, 1 barrier/tile);
// perm preloaded once to smem. Q in registers; K/P via ldmatrix; V via
// ldmatrix.trans. Softmax fp32 on fragments.
// ---------------------------------------------------------------------------
constexpr int KSH = 72;                           // stride in halves (144B)
constexpr int KV_TILE_B = 64 * KSH * 2;           // 9216 B (one K or V tile)
constexpr int KV_STAGE_B = 2 * KV_TILE_B;         // 18432 B (K+V)
constexpr int PS_OFF   = 3 * KV_STAGE_B;          // 55296
constexpr int PERM_OFF = PS_OFF + 128 * KSH * 2;  // 73728
constexpr int ATTN_SMEM = PERM_OFF + Tt * 4;      // 81920 B

__global__ __launch_bounds__(256, 2) void attn_mma(
    const __half* __restrict__ qkv, const int* __restrict__ perm,
    __half* __restrict__ out) {
    extern __shared__ __half smem_a[];
    uint32_t sb = smem_u32(smem_a);
    __half* Ps    = (__half*)((char*)smem_a + PS_OFF);
    int*    permS = (int*)((char*)smem_a + PERM_OFF);

    int tid = threadIdx.x, lane = tid & 31, w = tid >> 5;
    int r = lane >> 2, c = lane & 3;
    int q0 = blockIdx.x * 128;
    int h = blockIdx.y, b = blockIdx.z;

    uint32_t psBase = sb + (uint32_t)PS_OFF;

    int frow = ((lane >> 3) & 1) * 8 + (lane & 7);
    int fcol = (lane >> 4) * 8;

    // Preload perm (whole T) once
    #pragma unroll
    for (int i = 0; i < 2; i++)
        ((int4*)permS)[tid + i * 256] = ((const int4*)perm)[tid + i * 256];

    // KV tile loader: K 64x64 + V 64x64 halves = 1024 cp16 chunks, 4/thread
    auto loadKV = [&](int st, int t) {
        int k0 = t * 64;
        uint32_t base = sb + (uint32_t)(st * KV_STAGE_B);
        #pragma unroll
        for (int i = 0; i < 4; i++) {
            int ch = tid + i * 256;
            int which = ch >> 9;            // 0 = K, 1 = V
            int idx = ch & 511;
            int rr = idx >> 3, c8 = idx & 7;
            const __half* src = qkv + ((size_t)(b * Tt + k0 + rr)) * 3072
                              + (which ? 2048 : 1024) + h * 64 + c8 * 8;
            cp16(base + (uint32_t)(which * KV_TILE_B)
                      + (uint32_t)(rr * KSH + c8 * 8) * 2u, src);
        }
    };

    // Q fragments (fp16)
    const __half* qb = qkv + ((size_t)(b * Tt + q0 + w * 16)) * 3072 + h * 64;
    uint32_t qa[4][4];
    #pragma unroll
    for (int j = 0; j < 4; j++) {
        qa[j][0] = *(const uint32_t*)&qb[(size_t)r * 3072 + j * 16 + 2 * c];
        qa[j][1] = *(const uint32_t*)&qb[(size_t)(r + 8) * 3072 + j * 16 + 2 * c];
        qa[j][2] = *(const uint32_t*)&qb[(size_t)r * 3072 + j * 16 + 8 + 2 * c];
        qa[j][3] = *(const uint32_t*)&qb[(size_t)(r + 8) * 3072 + j * 16 + 8 + 2 * c];
    }

    float oacc[8][4];
    #pragma unroll
    for (int i = 0; i < 8; i++)
        #pragma unroll
        for (int k = 0; k < 4; k++) oacc[i][k] = 0.f;
    float m0 = -1e30f, m1 = -1e30f, l0 = 0.f, l1 = 0.f;
    int q_lo = q0 + w * 16 + r, q_hi = q_lo + 8;
    __half* Pw = Ps + (w * 16) * KSH;
    uint32_t pwBase = psBase + (uint32_t)((w * 16) * KSH) * 2u;

    constexpr int NT = Tt / 64;     // 32 tiles
    loadKV(0, 0);
    asm volatile("cp.async.commit_group;\n" ::: "memory");
    loadKV(1, 1);
    asm volatile("cp.async.commit_group;\n" ::: "memory");

    for (int t = 0; t < NT; t++) {
        int st = t % 3;
        asm volatile("cp.async.wait_group 1;\n" ::: "memory");
        __syncthreads();
        if (t + 2 < NT) loadKV((t + 2) % 3, t + 2);
        asm volatile("cp.async.commit_group;\n" ::: "memory");

        uint32_t ksBase = sb + (uint32_t)(st * KV_STAGE_B);
        uint32_t vsBase = ksBase + (uint32_t)KV_TILE_B;

        // S = Q @ K^T
        float sacc[8][4];
        #pragma unroll
        for (int i = 0; i < 8; i++)
            #pragma unroll
            for (int k = 0; k < 4; k++) sacc[i][k] = 0.f;
        #pragma unroll
        for (int j = 0; j < 4; j++) {
            #pragma unroll
            for (int np = 0; np < 4; np++) {
                uint32_t kb[4];
                ldsm_x4(kb, ksBase
                        + (uint32_t)((np * 16 + frow) * KSH + j * 16 + fcol) * 2u);
                mma_f16(sacc[np * 2],     qa[j], kb[0], kb[2]);
                mma_f16(sacc[np * 2 + 1], qa[j], kb[1], kb[3]);
            }
        }

        // Mask + scale + per-row max (perm from the preloaded smem array)
        const int* pT = permS + t * 64;
        float mx0 = -1e30f, mx1 = -1e30f;
        #pragma unroll
        for (int ni = 0; ni < 8; ni++) {
            int col = ni * 8 + 2 * c;
            int p0 = pT[col], p1 = pT[col + 1];
            sacc[ni][0] = (p0 > q_lo) ? -1e30f : sacc[ni][0] * 0.125f;
            sacc[ni][1] = (p1 > q_lo) ? -1e30f : sacc[ni][1] * 0.125f;
            sacc[ni][2] = (p0 > q_hi) ? -1e30f : sacc[ni][2] * 0.125f;
            sacc[ni][3] = (p1 > q_hi) ? -1e30f : sacc[ni][3] * 0.125f;
            mx0 = fmaxf(mx0, fmaxf(sacc[ni][0], sacc[ni][1]));
            mx1 = fmaxf(mx1, fmaxf(sacc[ni][2], sacc[ni][3]));
        }
        mx0 = fmaxf(mx0, __shfl_xor_sync(0xffffffffu, mx0, 1));
        mx0 = fmaxf(mx0, __shfl_xor_sync(0xffffffffu, mx0, 2));
        mx1 = fmaxf(mx1, __shfl_xor_sync(0xffffffffu, mx1, 1));
        mx1 = fmaxf(mx1, __shfl_xor_sync(0xffffffffu, mx1, 2));

        float nm0 = fmaxf(m0, mx0), nm1 = fmaxf(m1, mx1);
        float al0 = __expf(m0 - nm0), al1 = __expf(m1 - nm1);
        float ls0 = 0.f, ls1 = 0.f;
        #pragma unroll
        for (int ni = 0; ni < 8; ni++) {
            sacc[ni][0] = __expf(sacc[ni][0] - nm0);
            sacc[ni][1] = __expf(sacc[ni][1] - nm0);
            sacc[ni][2] = __expf(sacc[ni][2] - nm1);
            sacc[ni][3] = __expf(sacc[ni][3] - nm1);
            ls0 += sacc[ni][0] + sacc[ni][1];
            ls1 += sacc[ni][2] + sacc[ni][3];
        }
        ls0 += __shfl_xor_sync(0xffffffffu, ls0, 1);
        ls0 += __shfl_xor_sync(0xffffffffu, ls0, 2);
        ls1 += __shfl_xor_sync(0xffffffffu, ls1, 1);
        ls1 += __shfl_xor_sync(0xffffffffu, ls1, 2);
        l0 = l0 * al0 + ls0;
        l1 = l1 * al1 + ls1;
        m0 = nm0; m1 = nm1;
        #pragma unroll
        for (int ni = 0; ni < 8; ni++) {
            oacc[ni][0] *= al0; oacc[ni][1] *= al0;
            oacc[ni][2] *= al1; oacc[ni][3] *= al1;
        }

        // P (fp16) to per-warp smem in C-frag layout
        #pragma unroll
        for (int ni = 0; ni < 8; ni++) {
            int col = ni * 8 + 2 * c;
            *(__half2*)&Pw[r * KSH + col]       = __floats2half2_rn(sacc[ni][0], sacc[ni][1]);
            *(__half2*)&Pw[(r + 8) * KSH + col] = __floats2half2_rn(sacc[ni][2], sacc[ni][3]);
        }
        __syncwarp();

        // O += P @ V
        #pragma unroll
        for (int j = 0; j < 4; j++) {
            uint32_t pa[4];
            ldsm_x4(pa, pwBase + (uint32_t)(frow * KSH + j * 16 + fcol) * 2u);
            #pragma unroll
            for (int db = 0; db < 4; db++) {
                uint32_t vb[4];
                ldsm_x4_t(vb, vsBase
                          + (uint32_t)((j * 16 + frow) * KSH + db * 16 + fcol) * 2u);
                mma_f16(oacc[db * 2],     pa, vb[0], vb[1]);
                mma_f16(oacc[db * 2 + 1], pa, vb[2], vb[3]);
            }
        }
    }

    float inv0 = 1.0f / l0, inv1 = 1.0f / l1;
    __half* ob = out + ((size_t)(b * Tt + q_lo)) * 1024 + h * 64;
    #pragma unroll
    for (int ni = 0; ni < 8; ni++) {
        int col = ni * 8 + 2 * c;
        *(__half2*)&ob[col] = __floats2half2_rn(oacc[ni][0] * inv0, oacc[ni][1] * inv0);
        *(__half2*)&ob[(size_t)8 * 1024 + col] =
            __floats2half2_rn(oacc[ni][2] * inv1, oacc[ni][3] * inv1);
    }
}

// ---------------------------------------------------------------------------
// Launch
// ---------------------------------------------------------------------------
extern "C" void kernel_launch(void* const* d_in, const int* in_sizes, int n_in,
                              void* d_out, int out_size) {
    (void)in_sizes; (void)n_in; (void)out_size;
    const float* x     = (const float*)d_in[0];
    const int*   perm  = (const int*)d_in[1];
    const float* Wqkv  = (const float*)d_in[2];
    const float* Wproj = (const float*)d_in[3];
    const float* bproj = (const float*)d_in[4];
    const float* ln1_g = (const float*)d_in[5];
    const float* ln1_b = (const float*)d_in[6];
    const float* ln2_g = (const float*)d_in[7];
    const float* ln2_b = (const float*)d_in[8];
    const float* Wff1  = (const float*)d_in[9];
    const float* bff1  = (const float*)d_in[10];
    const float* Wff2  = (const float*)d_in[11];
    const float* bff2  = (const float*)d_in[12];
    float* out = (float*)d_out;

    void *ph, *pqkv, *patt, *px2, *pff, *pwq, *pwp, *pw1, *pw2;
    cudaGetSymbolAddress(&ph,   g_h);
    cudaGetSymbolAddress(&pqkv, g_qkv);
    cudaGetSymbolAddress(&patt, g_att);
    cudaGetSymbolAddress(&px2,  g_x2);
    cudaGetSymbolAddress(&pff,  g_ff);
    cudaGetSymbolAddress(&pwq,  g_wqkvT);
    cudaGetSymbolAddress(&pwp,  g_wprojT);
    cudaGetSymbolAddress(&pw1,  g_wff1T);
    cudaGetSymbolAddress(&pw2,  g_wff2T);
    __half* h   = (__half*)ph;
    __half* qkv = (__half*)pqkv;
    __half* att = (__half*)patt;
    float*  x2  = (float*)px2;
    __half* ff  = (__half*)pff;
    __half* wqT = (__half*)pwq;
    __half* wpT = (__half*)pwp;
    __half* w1T = (__half*)pw1;
    __half* w2T = (__half*)pw2;

    cudaFuncSetAttribute((const void*)tgemm<0>,
                         cudaFuncAttributeMaxDynamicSharedMemorySize, GEMM_SMEM);
    cudaFuncSetAttribute((const void*)tgemm<1>,
                         cudaFuncAttributeMaxDynamicSharedMemorySize, GEMM_SMEM);
    cudaFuncSetAttribute((const void*)tgemm<2>,
                         cudaFuncAttributeMaxDynamicSharedMemorySize, GEMM_SMEM);
    cudaFuncSetAttribute((const void*)attn_mma,
                         cudaFuncAttributeMaxDynamicSharedMemorySize, ATTN_SMEM);

    // 0. Weight transpose + fp16 convert
    {
        dim3 blk(32, 8);
        round_wT_kernel<<<dim3(3 * Cc / 32, Cc / 32), blk>>>(Wqkv,  wqT, Cc,  3 * Cc);
        round_wT_kernel<<<dim3(Cc / 32, Cc / 32),     blk>>>(Wproj, wpT, Cc,  Cc);
        round_wT_kernel<<<dim3(FFf / 32, Cc / 32),    blk>>>(Wff1,  w1T, Cc,  FFf);
        round_wT_kernel<<<dim3(Cc / 32, FFf / 32),    blk>>>(Wff2,  w2T, FFf, Cc);
    }

    // 1. h = LN1(x)
    ln_kernel<<<Mm, 256>>>(x, ln1_g, ln1_b, h);
    // 2. qkv = h @ Wqkv
    tgemm<0><<<dim3(3 * Cc / 128, Mm / 128), 256, GEMM_SMEM>>>(
        h, wqT, nullptr, nullptr, qkv, Mm, 3 * Cc, Cc);
    // 3. attention -> att
    attn_mma<<<dim3(Tt / 128, Hh, Bb), 256, ATTN_SMEM>>>(qkv, perm, att);
    // 4. x2 = x + att @ Wproj + bproj
    tgemm<1><<<dim3(Cc / 128, Mm / 128), 256, GEMM_SMEM>>>(
        att, wpT, bproj, x, x2, Mm, Cc, Cc);
    // 5. h = LN2(x2)
    ln_kernel<<<Mm, 256>>>(x2, ln2_g, ln2_b, h);
    // 6. ff = gelu(h @ Wff1 + bff1)
    tgemm<2><<<dim3(FFf / 128, Mm / 128), 256, GEMM_SMEM>>>(
        h, w1T, bff1, nullptr, ff, Mm, FFf, Cc);
    // 7. out = x2 + ff @ Wff2 + bff2
    tgemm<1><<<dim3(Cc / 128, Mm / 128), 256, GEMM_SMEM>>>(
        ff, w2T, bff2, x2, out, Mm, Cc, FFf);
}

// round 14
// speedup vs baseline: 3.0272x; 1.0264x over previous
#include <cuda_runtime.h>
#include <cuda_fp16.h>
#include <math.h>
#include <stdint.h>

// Problem constants
constexpr int Bb = 4;
constexpr int Tt = 2048;
constexpr int Cc = 1024;
constexpr int Hh = 16;
constexpr int Dd = 64;
constexpr int FFf = 2048;
constexpr int Mm = Bb * Tt;   // 8192

// ---------------------------------------------------------------------------
// Scratch (device globals; no allocation allowed)
// ---------------------------------------------------------------------------
__device__ __half g_h   [(size_t)Mm * Cc];
__device__ __half g_qkv [(size_t)Mm * 3 * Cc];
__device__ __half g_att [(size_t)Mm * Cc];
__device__ float  g_x2  [(size_t)Mm * Cc];
__device__ __half g_ff  [(size_t)Mm * FFf];
__device__ __half g_wqkvT [(size_t)3 * Cc * Cc];
__device__ __half g_wprojT[(size_t)Cc * Cc];
__device__ __half g_wff1T [(size_t)FFf * Cc];
__device__ __half g_wff2T [(size_t)Cc * FFf];

// ---------------------------------------------------------------------------
// Helpers
// ---------------------------------------------------------------------------
__device__ __forceinline__ void mma_f16(float* c, const uint32_t* a,
                                        uint32_t b0, uint32_t b1) {
    asm volatile(
        "mma.sync.aligned.m16n8k16.row.col.f32.f16.f16.f32 "
        "{%0,%1,%2,%3}, {%4,%5,%6,%7}, {%8,%9}, {%0,%1,%2,%3};\n"
        : "+f"(c[0]), "+f"(c[1]), "+f"(c[2]), "+f"(c[3])
        : "r"(a[0]), "r"(a[1]), "r"(a[2]), "r"(a[3]), "r"(b0), "r"(b1));
}

__device__ __forceinline__ void cp16(uint32_t saddr, const void* g) {
    asm volatile("cp.async.cg.shared.global [%0], [%1], 16;\n" :: "r"(saddr), "l"(g));
}

__device__ __forceinline__ void ldsm_x4(uint32_t* r, uint32_t addr) {
    asm volatile("ldmatrix.sync.aligned.m8n8.x4.shared.b16 {%0,%1,%2,%3}, [%4];\n"
                 : "=r"(r[0]), "=r"(r[1]), "=r"(r[2]), "=r"(r[3]) : "r"(addr));
}
__device__ __forceinline__ void ldsm_x4_t(uint32_t* r, uint32_t addr) {
    asm volatile("ldmatrix.sync.aligned.m8n8.x4.trans.shared.b16 {%0,%1,%2,%3}, [%4];\n"
                 : "=r"(r[0]), "=r"(r[1]), "=r"(r[2]), "=r"(r[3]) : "r"(addr));
}

__device__ __forceinline__ uint32_t smem_u32(const void* p) {
    return (uint32_t)__cvta_generic_to_shared(p);
}

__device__ __forceinline__ uint32_t h2bits(float a, float b) {
    __half2 h = __floats2half2_rn(a, b);
    return *reinterpret_cast<uint32_t*>(&h);
}

// ---------------------------------------------------------------------------
// Weight transpose + fp16 convert, ALL FOUR weights in one launch.
// Tile counts: wqkv 96x32=3072, wproj 32x32=1024, wff1 64x32=2048,
// wff2 32x64=2048 -> grid 8192.
// ---------------------------------------------------------------------------
__global__ void round_wT_all(const float* __restrict__ s0, __half* __restrict__ d0,
                             const float* __restrict__ s1, __half* __restrict__ d1,
                             const float* __restrict__ s2, __half* __restrict__ d2,
                             const float* __restrict__ s3, __half* __restrict__ d3) {
    __shared__ float t[32][33];
    int id = blockIdx.x;
    const float* src; __half* dst; int K, N, nxT;
    if (id < 3072)      { src = s0; dst = d0; K = 1024; N = 3072; nxT = 96; }
    else if (id < 4096) { id -= 3072; src = s1; dst = d1; K = 1024; N = 1024; nxT = 32; }
    else if (id < 6144) { id -= 4096; src = s2; dst = d2; K = 1024; N = 2048; nxT = 64; }
    else                { id -= 6144; src = s3; dst = d3; K = 2048; N = 1024; nxT = 32; }
    int nx = (id % nxT) * 32, ky = (id / nxT) * 32;
    #pragma unroll
    for (int i = 0; i < 4; i++) {
        int k = ky + threadIdx.y + i * 8;
        t[threadIdx.y + i * 8][threadIdx.x] = src[(size_t)k * N + nx + threadIdx.x];
    }
    __syncthreads();
    #pragma unroll
    for (int i = 0; i < 4; i++) {
        int n = nx + threadIdx.y + i * 8;
        dst[(size_t)n * K + ky + threadIdx.x] =
            __float2half_rn(t[threadIdx.x][threadIdx.y + i * 8]);
    }
}

// ---------------------------------------------------------------------------
// LayerNorm: fp32 in, fp16 out. One block per row, 256 threads.
// ---------------------------------------------------------------------------
__global__ void ln_kernel(const float* __restrict__ x,
                          const float* __restrict__ gamma,
                          const float* __restrict__ beta,
                          __half* __restrict__ out) {
    int row = blockIdx.x;
    int tid = threadIdx.x;
    const float4* xr = (const float4*)(x + (size_t)row * Cc);
    float4 v = xr[tid];

    float s  = v.x + v.y + v.z + v.w;
    float sq = v.x * v.x + v.y * v.y + v.z * v.z + v.w * v.w;
    #pragma unroll
    for (int o = 16; o > 0; o >>= 1) {
        s  += __shfl_xor_sync(0xffffffffu, s,  o);
        sq += __shfl_xor_sync(0xffffffffu, sq, o);
    }
    __shared__ float ss[8], ssq[8];
    __shared__ float mu_s, rs_s;
    int w = tid >> 5;
    if ((tid & 31) == 0) { ss[w] = s; ssq[w] = sq; }
    __syncthreads();
    if (tid == 0) {
        float S = 0.f, SQ = 0.f;
        #pragma unroll
        for (int i = 0; i < 8; i++) { S += ss[i]; SQ += ssq[i]; }
        float mu  = S * (1.0f / (float)Cc);
        float var = SQ * (1.0f / (float)Cc) - mu * mu;
        mu_s = mu;
        rs_s = rsqrtf(var + 1e-5f);
    }
    __syncthreads();
    float mu = mu_s, rs = rs_s;
    float4 gv = ((const float4*)gamma)[tid];
    float4 bv = ((const float4*)beta)[tid];
    __half2 h0 = __floats2half2_rn((v.x - mu) * rs * gv.x + bv.x,
                                   (v.y - mu) * rs * gv.y + bv.y);
    __half2 h1 = __floats2half2_rn((v.z - mu) * rs * gv.z + bv.z,
                                   (v.w - mu) * rs * gv.w + bv.w);
    __half2* op = (__half2*)(out + (size_t)row * Cc + tid * 4);
    op[0] = h0;
    op[1] = h1;
}

// ---------------------------------------------------------------------------
// fp16 tensor-core GEMM (unchanged from R13 best): BM=BN=128, BK=64,
// 256 threads, 3-stage cp.async, 2 CTAs/SM.
// EPI: 0 = fp16 out (qkv), 1 = +bias+residual fp32 out, 2 = +bias GELU fp16.
// ---------------------------------------------------------------------------
constexpr int GS = 72;                              // smem stride halves (144B)
constexpr int TILE_B = 128 * GS * 2;                // 18432 bytes per tile
constexpr int STAGE_B = 2 * TILE_B;                 // 36864 bytes (A+B)
constexpr int GEMM_SMEM = 3 * STAGE_B;              // 110592 bytes

template <int EPI>
__global__ __launch_bounds__(256, 2) void tgemm(
    const __half* __restrict__ A, const __half* __restrict__ Bt,
    const float* __restrict__ bias, const float* __restrict__ res,
    void* __restrict__ CoutV, int Mn, int Nn, int Kn) {
    extern __shared__ __half smem_g[];

    int tid = threadIdx.x, lane = tid & 31, w = tid >> 5;
    int wm = w >> 2, wn = w & 3;
    int row0 = blockIdx.y * 128, col0 = blockIdx.x * 128;
    int r = lane >> 2, c = lane & 3;

    float acc[4][4][4];
    #pragma unroll
    for (int i = 0; i < 4; i++)
        #pragma unroll
        for (int j = 0; j < 4; j++)
            #pragma unroll
            for (int k = 0; k < 4; k++) acc[i][j][k] = 0.f;

    uint32_t sb = smem_u32(smem_g);

    int frow = ((lane >> 3) & 1) * 8 + (lane & 7);
    int fcol = (lane >> 4) * 8;
    uint32_t laneOff = (uint32_t)(frow * GS + fcol) * 2u;

    const __half* Ap = A + (size_t)row0 * Kn;
    const __half* Bp = Bt + (size_t)col0 * Kn;

    auto loadT = [&](int st, int kt) {
        int k0 = kt * 64;
        uint32_t base = sb + (uint32_t)(st * STAGE_B);
        #pragma unroll
        for (int i = 0; i < 8; i++) {
            int ch = tid + i * 256;
            int which = ch >> 10;
            int idx = ch & 1023;
            int rr = idx >> 3, c8 = idx & 7;
            const __half* src = which ? Bp : Ap;
            cp16(base + (uint32_t)(which * TILE_B) + (uint32_t)(rr * GS + c8 * 8) * 2u,
                 src + (size_t)rr * Kn + k0 + c8 * 8);
        }
    };

    int nk = Kn >> 6;
    loadT(0, 0);
    asm volatile("cp.async.commit_group;\n" ::: "memory");
    loadT(1, 1);
    asm volatile("cp.async.commit_group;\n" ::: "memory");

    for (int kt = 0; kt < nk; kt++) {
        int st = kt % 3;
        asm volatile("cp.async.wait_group 1;\n" ::: "memory");
        __syncthreads();
        if (kt + 2 < nk) loadT((kt + 2) % 3, kt + 2);
        asm volatile("cp.async.commit_group;\n" ::: "memory");

        uint32_t aStage = sb + (uint32_t)(st * STAGE_B) + laneOff;
        uint32_t bStage = aStage + (uint32_t)TILE_B;
        #pragma unroll
        for (int kk = 0; kk < 4; kk++) {
            int kh = kk * 16;
            uint32_t af[4][4], bfr[2][4];
            #pragma unroll
            for (int mi = 0; mi < 4; mi++)
                ldsm_x4(af[mi], aStage + (uint32_t)((wm * 64 + mi * 16) * GS + kh) * 2u);
            #pragma unroll
            for (int g = 0; g < 2; g++)
                ldsm_x4(bfr[g], bStage + (uint32_t)((wn * 32 + g * 16) * GS + kh) * 2u);
            #pragma unroll
            for (int mi = 0; mi < 4; mi++)
                #pragma unroll
                for (int ni = 0; ni < 4; ni++) {
                    int g = ni >> 1, p = ni & 1;
                    mma_f16(acc[mi][ni], af[mi], bfr[g][0 + p], bfr[g][2 + p]);
                }
        }
        __syncthreads();
    }

    #pragma unroll
    for (int mi = 0; mi < 4; mi++) {
        int rr0 = row0 + wm * 64 + mi * 16 + r;
        #pragma unroll
        for (int ni = 0; ni < 4; ni++) {
            int cc = col0 + wn * 32 + ni * 8 + 2 * c;
            float v0 = acc[mi][ni][0], v1 = acc[mi][ni][1];
            float v2 = acc[mi][ni][2], v3 = acc[mi][ni][3];
            if constexpr (EPI == 0) {
                __half* Cout = (__half*)CoutV;
                *(__half2*)&Cout[(size_t)rr0 * Nn + cc]       = __floats2half2_rn(v0, v1);
                *(__half2*)&Cout[(size_t)(rr0 + 8) * Nn + cc] = __floats2half2_rn(v2, v3);
            } else if constexpr (EPI == 1) {
                float* Cout = (float*)CoutV;
                float b0 = bias[cc], b1 = bias[cc + 1];
                float2 r0 = *(const float2*)&res[(size_t)rr0 * Nn + cc];
                float2 r1 = *(const float2*)&res[(size_t)(rr0 + 8) * Nn + cc];
                *(float2*)&Cout[(size_t)rr0 * Nn + cc] =
                    make_float2(v0 + b0 + r0.x, v1 + b1 + r0.y);
                *(float2*)&Cout[(size_t)(rr0 + 8) * Nn + cc] =
                    make_float2(v2 + b0 + r1.x, v3 + b1 + r1.y);
            } else {
                __half* Cout = (__half*)CoutV;
                float b0 = bias[cc], b1 = bias[cc + 1];
                v0 += b0; v1 += b1; v2 += b0; v3 += b1;
                v0 = 0.5f * v0 * (1.0f + erff(v0 * 0.70710678118654752f));
                v1 = 0.5f * v1 * (1.0f + erff(v1 * 0.70710678118654752f));
                v2 = 0.5f * v2 * (1.0f + erff(v2 * 0.70710678118654752f));
                v3 = 0.5f * v3 * (1.0f + erff(v3 * 0.70710678118654752f));
                *(__half2*)&Cout[(size_t)rr0 * Nn + cc]       = __floats2half2_rn(v0, v1);
                *(__half2*)&Cout[(size_t)(rr0 + 8) * Nn + cc] = __floats2half2_rn(v2, v3);
            }
        }
    }
}

// ---------------------------------------------------------------------------
// fp16 flash attention with permutation mask.
// 128 queries/block (8 warps x 16 rows), KV tiles of 64, D=64.
// K/V via 3-stage cp.async ring; perm preloaded once.
// NEW: P stays in registers — the S C-fragment is repacked directly into
// the PV A-fragment (identical lane mapping), no smem round-trip.
// ---------------------------------------------------------------------------
constexpr int KSH = 72;                           // stride in halves (144B)
constexpr int KV_TILE_B = 64 * KSH * 2;           // 9216 B (one K or V tile)
constexpr int KV_STAGE_B = 2 * KV_TILE_B;         // 18432 B (K+V)
constexpr int PERM_OFF = 3 * KV_STAGE_B;          // 55296
constexpr int ATTN_SMEM = PERM_OFF + Tt * 4;      // 63488 B

__global__ __launch_bounds__(256, 2) void attn_mma(
    const __half* __restrict__ qkv, const int* __restrict__ perm,
    __half* __restrict__ out) {
    extern __shared__ __half smem_a[];
    uint32_t sb = smem_u32(smem_a);
    int* permS = (int*)((char*)smem_a + PERM_OFF);

    int tid = threadIdx.x, lane = tid & 31, w = tid >> 5;
    int r = lane >> 2, c = lane & 3;
    int q0 = blockIdx.x * 128;
    int h = blockIdx.y, b = blockIdx.z;

    int frow = ((lane >> 3) & 1) * 8 + (lane & 7);
    int fcol = (lane >> 4) * 8;

    // Preload perm (whole T) once
    #pragma unroll
    for (int i = 0; i < 2; i++)
        ((int4*)permS)[tid + i * 256] = ((const int4*)perm)[tid + i * 256];

    auto loadKV = [&](int st, int t) {
        int k0 = t * 64;
        uint32_t base = sb + (uint32_t)(st * KV_STAGE_B);
        #pragma unroll
        for (int i = 0; i < 4; i++) {
            int ch = tid + i * 256;
            int which = ch >> 9;
            int idx = ch & 511;
            int rr = idx >> 3, c8 = idx & 7;
            const __half* src = qkv + ((size_t)(b * Tt + k0 + rr)) * 3072
                              + (which ? 2048 : 1024) + h * 64 + c8 * 8;
            cp16(base + (uint32_t)(which * KV_TILE_B)
                      + (uint32_t)(rr * KSH + c8 * 8) * 2u, src);
        }
    };

    // Q fragments (fp16)
    const __half* qb = qkv + ((size_t)(b * Tt + q0 + w * 16)) * 3072 + h * 64;
    uint32_t qa[4][4];
    #pragma unroll
    for (int j = 0; j < 4; j++) {
        qa[j][0] = *(const uint32_t*)&qb[(size_t)r * 3072 + j * 16 + 2 * c];
        qa[j][1] = *(const uint32_t*)&qb[(size_t)(r + 8) * 3072 + j * 16 + 2 * c];
        qa[j][2] = *(const uint32_t*)&qb[(size_t)r * 3072 + j * 16 + 8 + 2 * c];
        qa[j][3] = *(const uint32_t*)&qb[(size_t)(r + 8) * 3072 + j * 16 + 8 + 2 * c];
    }

    float oacc[8][4];
    #pragma unroll
    for (int i = 0; i < 8; i++)
        #pragma unroll
        for (int k = 0; k < 4; k++) oacc[i][k] = 0.f;
    float m0 = -1e30f, m1 = -1e30f, l0 = 0.f, l1 = 0.f;
    int q_lo = q0 + w * 16 + r, q_hi = q_lo + 8;

    constexpr int NT = Tt / 64;     // 32 tiles
    loadKV(0, 0);
    asm volatile("cp.async.commit_group;\n" ::: "memory");
    loadKV(1, 1);
    asm volatile("cp.async.commit_group;\n" ::: "memory");

    for (int t = 0; t < NT; t++) {
        int st = t % 3;
        asm volatile("cp.async.wait_group 1;\n" ::: "memory");
        __syncthreads();
        if (t + 2 < NT) loadKV((t + 2) % 3, t + 2);
        asm volatile("cp.async.commit_group;\n" ::: "memory");

        uint32_t ksBase = sb + (uint32_t)(st * KV_STAGE_B);
        uint32_t vsBase = ksBase + (uint32_t)KV_TILE_B;

        // S = Q @ K^T
        float sacc[8][4];
        #pragma unroll
        for (int i = 0; i < 8; i++)
            #pragma unroll
            for (int k = 0; k < 4; k++) sacc[i][k] = 0.f;
        #pragma unroll
        for (int j = 0; j < 4; j++) {
            #pragma unroll
            for (int np = 0; np < 4; np++) {
                uint32_t kb[4];
                ldsm_x4(kb, ksBase
                        + (uint32_t)((np * 16 + frow) * KSH + j * 16 + fcol) * 2u);
                mma_f16(sacc[np * 2],     qa[j], kb[0], kb[2]);
                mma_f16(sacc[np * 2 + 1], qa[j], kb[1], kb[3]);
            }
        }

        // Mask + scale + per-row max
        const int* pT = permS + t * 64;
        float mx0 = -1e30f, mx1 = -1e30f;
        #pragma unroll
        for (int ni = 0; ni < 8; ni++) {
            int col = ni * 8 + 2 * c;
            int p0 = pT[col], p1 = pT[col + 1];
            sacc[ni][0] = (p0 > q_lo) ? -1e30f : sacc[ni][0] * 0.125f;
            sacc[ni][1] = (p1 > q_lo) ? -1e30f : sacc[ni][1] * 0.125f;
            sacc[ni][2] = (p0 > q_hi) ? -1e30f : sacc[ni][2] * 0.125f;
            sacc[ni][3] = (p1 > q_hi) ? -1e30f : sacc[ni][3] * 0.125f;
            mx0 = fmaxf(mx0, fmaxf(sacc[ni][0], sacc[ni][1]));
            mx1 = fmaxf(mx1, fmaxf(sacc[ni][2], sacc[ni][3]));
        }
        mx0 = fmaxf(mx0, __shfl_xor_sync(0xffffffffu, mx0, 1));
        mx0 = fmaxf(mx0, __shfl_xor_sync(0xffffffffu, mx0, 2));
        mx1 = fmaxf(mx1, __shfl_xor_sync(0xffffffffu, mx1, 1));
        mx1 = fmaxf(mx1, __shfl_xor_sync(0xffffffffu, mx1, 2));

        float nm0 = fmaxf(m0, mx0), nm1 = fmaxf(m1, mx1);
        float al0 = __expf(m0 - nm0), al1 = __expf(m1 - nm1);
        float ls0 = 0.f, ls1 = 0.f;
        #pragma unroll
        for (int ni = 0; ni < 8; ni++) {
            sacc[ni][0] = __expf(sacc[ni][0] - nm0);
            sacc[ni][1] = __expf(sacc[ni][1] - nm0);
            sacc[ni][2] = __expf(sacc[ni][2] - nm1);
            sacc[ni][3] = __expf(sacc[ni][3] - nm1);
            ls0 += sacc[ni][0] + sacc[ni][1];
            ls1 += sacc[ni][2] + sacc[ni][3];
        }
        ls0 += __shfl_xor_sync(0xffffffffu, ls0, 1);
        ls0 += __shfl_xor_sync(0xffffffffu, ls0, 2);
        ls1 += __shfl_xor_sync(0xffffffffu, ls1, 1);
        ls1 += __shfl_xor_sync(0xffffffffu, ls1, 2);
        l0 = l0 * al0 + ls0;
        l1 = l1 * al1 + ls1;
        m0 = nm0; m1 = nm1;
        #pragma unroll
        for (int ni = 0; ni < 8; ni++) {
            oacc[ni][0] *= al0; oacc[ni][1] *= al0;
            oacc[ni][2] *= al1; oacc[ni][3] *= al1;
        }

        // O += P @ V : pack P A-frags DIRECTLY from the S C-frags.
        // k16-chunk j keys [16j,16j+16): a0=(r, 16j+2c..+1)=s[2j][0..1],
        // a1=(r+8,·)=s[2j][2..3], a2=(r, 16j+8+2c)=s[2j+1][0..1],
        // a3=(r+8,·)=s[2j+1][2..3].  V-frags via ldmatrix.trans.
        #pragma unroll
        for (int j = 0; j < 4; j++) {
            uint32_t pa[4];
            pa[0] = h2bits(sacc[2 * j][0],     sacc[2 * j][1]);
            pa[1] = h2bits(sacc[2 * j][2],     sacc[2 * j][3]);
            pa[2] = h2bits(sacc[2 * j + 1][0], sacc[2 * j + 1][1]);
            pa[3] = h2bits(sacc[2 * j + 1][2], sacc[2 * j + 1][3]);
            #pragma unroll
            for (int db = 0; db < 4; db++) {
                uint32_t vb[4];
                ldsm_x4_t(vb, vsBase
                          + (uint32_t)((j * 16 + frow) * KSH + db * 16 + fcol) * 2u);
                mma_f16(oacc[db * 2],     pa, vb[0], vb[1]);
                mma_f16(oacc[db * 2 + 1], pa, vb[2], vb[3]);
            }
        }
    }

    float inv0 = 1.0f / l0, inv1 = 1.0f / l1;
    __half* ob = out + ((size_t)(b * Tt + q_lo)) * 1024 + h * 64;
    #pragma unroll
    for (int ni = 0; ni < 8; ni++) {
        int col = ni * 8 + 2 * c;
        *(__half2*)&ob[col] = __floats2half2_rn(oacc[ni][0] * inv0, oacc[ni][1] * inv0);
        *(__half2*)&ob[(size_t)8 * 1024 + col] =
            __floats2half2_rn(oacc[ni][2] * inv1, oacc[ni][3] * inv1);
    }
}

// ---------------------------------------------------------------------------
// Launch
// ---------------------------------------------------------------------------
extern "C" void kernel_launch(void* const* d_in, const int* in_sizes, int n_in,
                              void* d_out, int out_size) {
    (void)in_sizes; (void)n_in; (void)out_size;
    const float* x     = (const float*)d_in[0];
    const int*   perm  = (const int*)d_in[1];
    const float* Wqkv  = (const float*)d_in[2];
    const float* Wproj = (const float*)d_in[3];
    const float* bproj = (const float*)d_in[4];
    const float* ln1_g = (const float*)d_in[5];
    const float* ln1_b = (const float*)d_in[6];
    const float* ln2_g = (const float*)d_in[7];
    const float* ln2_b = (const float*)d_in[8];
    const float* Wff1  = (const float*)d_in[9];
    const float* bff1  = (const float*)d_in[10];
    const float* Wff2  = (const float*)d_in[11];
    const float* bff2  = (const float*)d_in[12];
    float* out = (float*)d_out;

    void *ph, *pqkv, *patt, *px2, *pff, *pwq, *pwp, *pw1, *pw2;
    cudaGetSymbolAddress(&ph,   g_h);
    cudaGetSymbolAddress(&pqkv, g_qkv);
    cudaGetSymbolAddress(&patt, g_att);
    cudaGetSymbolAddress(&px2,  g_x2);
    cudaGetSymbolAddress(&pff,  g_ff);
    cudaGetSymbolAddress(&pwq,  g_wqkvT);
    cudaGetSymbolAddress(&pwp,  g_wprojT);
    cudaGetSymbolAddress(&pw1,  g_wff1T);
    cudaGetSymbolAddress(&pw2,  g_wff2T);
    __half* h   = (__half*)ph;
    __half* qkv = (__half*)pqkv;
    __half* att = (__half*)patt;
    float*  x2  = (float*)px2;
    __half* ff  = (__half*)pff;
    __half* wqT = (__half*)pwq;
    __half* wpT = (__half*)pwp;
    __half* w1T = (__half*)pw1;
    __half* w2T = (__half*)pw2;

    cudaFuncSetAttribute((const void*)tgemm<0>,
                         cudaFuncAttributeMaxDynamicSharedMemorySize, GEMM_SMEM);
    cudaFuncSetAttribute((const void*)tgemm<1>,
                         cudaFuncAttributeMaxDynamicSharedMemorySize, GEMM_SMEM);
    cudaFuncSetAttribute((const void*)tgemm<2>,
                         cudaFuncAttributeMaxDynamicSharedMemorySize, GEMM_SMEM);
    cudaFuncSetAttribute((const void*)attn_mma,
                         cudaFuncAttributeMaxDynamicSharedMemorySize, ATTN_SMEM);

    // 0. Weight transpose + fp16 convert (single launch for all four)
    round_wT_all<<<8192, dim3(32, 8)>>>(Wqkv, wqT, Wproj, wpT, Wff1, w1T, Wff2, w2T);

    // 1. h = LN1(x)
    ln_kernel<<<Mm, 256>>>(x, ln1_g, ln1_b, h);
    // 2. qkv = h @ Wqkv
    tgemm<0><<<dim3(3 * Cc / 128, Mm / 128), 256, GEMM_SMEM>>>(
        h, wqT, nullptr, nullptr, qkv, Mm, 3 * Cc, Cc);
    // 3. attention -> att
    attn_mma<<<dim3(Tt / 128, Hh, Bb), 256, ATTN_SMEM>>>(qkv, perm, att);
    // 4. x2 = x + att @ Wproj + bproj
    tgemm<1><<<dim3(Cc / 128, Mm / 128), 256, GEMM_SMEM>>>(
        att, wpT, bproj, x, x2, Mm, Cc, Cc);
    // 5. h = LN2(x2)
    ln_kernel<<<Mm, 256>>>(x2, ln2_g, ln2_b, h);
    // 6. ff = gelu(h @ Wff1 + bff1)
    tgemm<2><<<dim3(FFf / 128, Mm / 128), 256, GEMM_SMEM>>>(
        h, w1T, bff1, nullptr, ff, Mm, FFf, Cc);
    // 7. out = x2 + ff @ Wff2 + bff2
    tgemm<1><<<dim3(Cc / 128, Mm / 128), 256, GEMM_SMEM>>>(
        ff, w2T, bff2, x2, out, Mm, Cc, FFf);
}

// round 16
// speedup vs baseline: 3.1717x; 1.0477x over previous
#include <cuda_runtime.h>
#include <cuda_fp16.h>
#include <math.h>
#include <stdint.h>

// Problem constants
constexpr int Bb = 4;
constexpr int Tt = 2048;
constexpr int Cc = 1024;
constexpr int Hh = 16;
constexpr int Dd = 64;
constexpr int FFf = 2048;
constexpr int Mm = Bb * Tt;   // 8192

// ---------------------------------------------------------------------------
// Scratch (device globals; no allocation allowed)
// ---------------------------------------------------------------------------
__device__ __half g_h   [(size_t)Mm * Cc];
__device__ __half g_qkv [(size_t)Mm * 3 * Cc];
__device__ __half g_att [(size_t)Mm * Cc];
__device__ float  g_x2  [(size_t)Mm * Cc];
__device__ __half g_ff  [(size_t)Mm * FFf];
__device__ __half g_wqkvT [(size_t)3 * Cc * Cc];
__device__ __half g_wprojT[(size_t)Cc * Cc];
__device__ __half g_wff1T [(size_t)FFf * Cc];
__device__ __half g_wff2T [(size_t)Cc * FFf];

// ---------------------------------------------------------------------------
// Helpers
// ---------------------------------------------------------------------------
__device__ __forceinline__ void mma_f16(float* c, const uint32_t* a,
                                        uint32_t b0, uint32_t b1) {
    asm volatile(
        "mma.sync.aligned.m16n8k16.row.col.f32.f16.f16.f32 "
        "{%0,%1,%2,%3}, {%4,%5,%6,%7}, {%8,%9}, {%0,%1,%2,%3};\n"
        : "+f"(c[0]), "+f"(c[1]), "+f"(c[2]), "+f"(c[3])
        : "r"(a[0]), "r"(a[1]), "r"(a[2]), "r"(a[3]), "r"(b0), "r"(b1));
}

__device__ __forceinline__ void cp16(uint32_t saddr, const void* g) {
    asm volatile("cp.async.cg.shared.global [%0], [%1], 16;\n" :: "r"(saddr), "l"(g));
}

__device__ __forceinline__ void ldsm_x4(uint32_t* r, uint32_t addr) {
    asm volatile("ldmatrix.sync.aligned.m8n8.x4.shared.b16 {%0,%1,%2,%3}, [%4];\n"
                 : "=r"(r[0]), "=r"(r[1]), "=r"(r[2]), "=r"(r[3]) : "r"(addr));
}
__device__ __forceinline__ void ldsm_x4_t(uint32_t* r, uint32_t addr) {
    asm volatile("ldmatrix.sync.aligned.m8n8.x4.trans.shared.b16 {%0,%1,%2,%3}, [%4];\n"
                 : "=r"(r[0]), "=r"(r[1]), "=r"(r[2]), "=r"(r[3]) : "r"(addr));
}

__device__ __forceinline__ uint32_t smem_u32(const void* p) {
    return (uint32_t)__cvta_generic_to_shared(p);
}

// pack (a,b) to fp16x2 and apply 2^x elementwise (ex2.approx.f16x2).
// P is consumed as fp16 anyway, so computing exp at fp16 precision matches
// the previous "fp32 exp then fp16 round" path to within ~1 ulp.
__device__ __forceinline__ uint32_t h2exp2_from(float a, float b) {
    __half2 h = __floats2half2_rn(a, b);
    uint32_t u = *reinterpret_cast<uint32_t*>(&h);
    uint32_t o;
    asm("ex2.approx.f16x2 %0, %1;\n" : "=r"(o) : "r"(u));
    return o;
}

constexpr uint32_t ONES_H2 = 0x3C003C00u;   // half2(1, 1)

// ---------------------------------------------------------------------------
// Weight transpose + fp16 convert, ALL FOUR weights in one launch.
// ---------------------------------------------------------------------------
__global__ void round_wT_all(const float* __restrict__ s0, __half* __restrict__ d0,
                             const float* __restrict__ s1, __half* __restrict__ d1,
                             const float* __restrict__ s2, __half* __restrict__ d2,
                             const float* __restrict__ s3, __half* __restrict__ d3) {
    __shared__ float t[32][33];
    int id = blockIdx.x;
    const float* src; __half* dst; int K, N, nxT;
    if (id < 3072)      { src = s0; dst = d0; K = 1024; N = 3072; nxT = 96; }
    else if (id < 4096) { id -= 3072; src = s1; dst = d1; K = 1024; N = 1024; nxT = 32; }
    else if (id < 6144) { id -= 4096; src = s2; dst = d2; K = 1024; N = 2048; nxT = 64; }
    else                { id -= 6144; src = s3; dst = d3; K = 2048; N = 1024; nxT = 32; }
    int nx = (id % nxT) * 32, ky = (id / nxT) * 32;
    #pragma unroll
    for (int i = 0; i < 4; i++) {
        int k = ky + threadIdx.y + i * 8;
        t[threadIdx.y + i * 8][threadIdx.x] = src[(size_t)k * N + nx + threadIdx.x];
    }
    __syncthreads();
    #pragma unroll
    for (int i = 0; i < 4; i++) {
        int n = nx + threadIdx.y + i * 8;
        dst[(size_t)n * K + ky + threadIdx.x] =
            __float2half_rn(t[threadIdx.x][threadIdx.y + i * 8]);
    }
}

// ---------------------------------------------------------------------------
// LayerNorm: fp32 in, fp16 out. One block per row, 256 threads.
// ---------------------------------------------------------------------------
__global__ void ln_kernel(const float* __restrict__ x,
                          const float* __restrict__ gamma,
                          const float* __restrict__ beta,
                          __half* __restrict__ out) {
    int row = blockIdx.x;
    int tid = threadIdx.x;
    const float4* xr = (const float4*)(x + (size_t)row * Cc);
    float4 v = xr[tid];

    float s  = v.x + v.y + v.z + v.w;
    float sq = v.x * v.x + v.y * v.y + v.z * v.z + v.w * v.w;
    #pragma unroll
    for (int o = 16; o > 0; o >>= 1) {
        s  += __shfl_xor_sync(0xffffffffu, s,  o);
        sq += __shfl_xor_sync(0xffffffffu, sq, o);
    }
    __shared__ float ss[8], ssq[8];
    __shared__ float mu_s, rs_s;
    int w = tid >> 5;
    if ((tid & 31) == 0) { ss[w] = s; ssq[w] = sq; }
    __syncthreads();
    if (tid == 0) {
        float S = 0.f, SQ = 0.f;
        #pragma unroll
        for (int i = 0; i < 8; i++) { S += ss[i]; SQ += ssq[i]; }
        float mu  = S * (1.0f / (float)Cc);
        float var = SQ * (1.0f / (float)Cc) - mu * mu;
        mu_s = mu;
        rs_s = rsqrtf(var + 1e-5f);
    }
    __syncthreads();
    float mu = mu_s, rs = rs_s;
    float4 gv = ((const float4*)gamma)[tid];
    float4 bv = ((const float4*)beta)[tid];
    __half2 h0 = __floats2half2_rn((v.x - mu) * rs * gv.x + bv.x,
                                   (v.y - mu) * rs * gv.y + bv.y);
    __half2 h1 = __floats2half2_rn((v.z - mu) * rs * gv.z + bv.z,
                                   (v.w - mu) * rs * gv.w + bv.w);
    __half2* op = (__half2*)(out + (size_t)row * Cc + tid * 4);
    op[0] = h0;
    op[1] = h1;
}

// ---------------------------------------------------------------------------
// fp16 tensor-core GEMM (unchanged R14 best): BM=BN=128, BK=64, 256 threads,
// 3-stage cp.async, 2 CTAs/SM.
// ---------------------------------------------------------------------------
constexpr int GS = 72;
constexpr int TILE_B = 128 * GS * 2;
constexpr int STAGE_B = 2 * TILE_B;
constexpr int GEMM_SMEM = 3 * STAGE_B;              // 110592 bytes

template <int EPI>
__global__ __launch_bounds__(256, 2) void tgemm(
    const __half* __restrict__ A, const __half* __restrict__ Bt,
    const float* __restrict__ bias, const float* __restrict__ res,
    void* __restrict__ CoutV, int Mn, int Nn, int Kn) {
    extern __shared__ __half smem_g[];

    int tid = threadIdx.x, lane = tid & 31, w = tid >> 5;
    int wm = w >> 2, wn = w & 3;
    int row0 = blockIdx.y * 128, col0 = blockIdx.x * 128;
    int r = lane >> 2, c = lane & 3;

    float acc[4][4][4];
    #pragma unroll
    for (int i = 0; i < 4; i++)
        #pragma unroll
        for (int j = 0; j < 4; j++)
            #pragma unroll
            for (int k = 0; k < 4; k++) acc[i][j][k] = 0.f;

    uint32_t sb = smem_u32(smem_g);

    int frow = ((lane >> 3) & 1) * 8 + (lane & 7);
    int fcol = (lane >> 4) * 8;
    uint32_t laneOff = (uint32_t)(frow * GS + fcol) * 2u;

    const __half* Ap = A + (size_t)row0 * Kn;
    const __half* Bp = Bt + (size_t)col0 * Kn;

    auto loadT = [&](int st, int kt) {
        int k0 = kt * 64;
        uint32_t base = sb + (uint32_t)(st * STAGE_B);
        #pragma unroll
        for (int i = 0; i < 8; i++) {
            int ch = tid + i * 256;
            int which = ch >> 10;
            int idx = ch & 1023;
            int rr = idx >> 3, c8 = idx & 7;
            const __half* src = which ? Bp : Ap;
            cp16(base + (uint32_t)(which * TILE_B) + (uint32_t)(rr * GS + c8 * 8) * 2u,
                 src + (size_t)rr * Kn + k0 + c8 * 8);
        }
    };

    int nk = Kn >> 6;
    loadT(0, 0);
    asm volatile("cp.async.commit_group;\n" ::: "memory");
    loadT(1, 1);
    asm volatile("cp.async.commit_group;\n" ::: "memory");

    for (int kt = 0; kt < nk; kt++) {
        int st = kt % 3;
        asm volatile("cp.async.wait_group 1;\n" ::: "memory");
        __syncthreads();
        if (kt + 2 < nk) loadT((kt + 2) % 3, kt + 2);
        asm volatile("cp.async.commit_group;\n" ::: "memory");

        uint32_t aStage = sb + (uint32_t)(st * STAGE_B) + laneOff;
        uint32_t bStage = aStage + (uint32_t)TILE_B;
        #pragma unroll
        for (int kk = 0; kk < 4; kk++) {
            int kh = kk * 16;
            uint32_t af[4][4], bfr[2][4];
            #pragma unroll
            for (int mi = 0; mi < 4; mi++)
                ldsm_x4(af[mi], aStage + (uint32_t)((wm * 64 + mi * 16) * GS + kh) * 2u);
            #pragma unroll
            for (int g = 0; g < 2; g++)
                ldsm_x4(bfr[g], bStage + (uint32_t)((wn * 32 + g * 16) * GS + kh) * 2u);
            #pragma unroll
            for (int mi = 0; mi < 4; mi++)
                #pragma unroll
                for (int ni = 0; ni < 4; ni++) {
                    int g = ni >> 1, p = ni & 1;
                    mma_f16(acc[mi][ni], af[mi], bfr[g][0 + p], bfr[g][2 + p]);
                }
        }
        __syncthreads();
    }

    #pragma unroll
    for (int mi = 0; mi < 4; mi++) {
        int rr0 = row0 + wm * 64 + mi * 16 + r;
        #pragma unroll
        for (int ni = 0; ni < 4; ni++) {
            int cc = col0 + wn * 32 + ni * 8 + 2 * c;
            float v0 = acc[mi][ni][0], v1 = acc[mi][ni][1];
            float v2 = acc[mi][ni][2], v3 = acc[mi][ni][3];
            if constexpr (EPI == 0) {
                __half* Cout = (__half*)CoutV;
                *(__half2*)&Cout[(size_t)rr0 * Nn + cc]       = __floats2half2_rn(v0, v1);
                *(__half2*)&Cout[(size_t)(rr0 + 8) * Nn + cc] = __floats2half2_rn(v2, v3);
            } else if constexpr (EPI == 1) {
                float* Cout = (float*)CoutV;
                float b0 = bias[cc], b1 = bias[cc + 1];
                float2 r0 = *(const float2*)&res[(size_t)rr0 * Nn + cc];
                float2 r1 = *(const float2*)&res[(size_t)(rr0 + 8) * Nn + cc];
                *(float2*)&Cout[(size_t)rr0 * Nn + cc] =
                    make_float2(v0 + b0 + r0.x, v1 + b1 + r0.y);
                *(float2*)&Cout[(size_t)(rr0 + 8) * Nn + cc] =
                    make_float2(v2 + b0 + r1.x, v3 + b1 + r1.y);
            } else {
                __half* Cout = (__half*)CoutV;
                float b0 = bias[cc], b1 = bias[cc + 1];
                v0 += b0; v1 += b1; v2 += b0; v3 += b1;
                v0 = 0.5f * v0 * (1.0f + erff(v0 * 0.70710678118654752f));
                v1 = 0.5f * v1 * (1.0f + erff(v1 * 0.70710678118654752f));
                v2 = 0.5f * v2 * (1.0f + erff(v2 * 0.70710678118654752f));
                v3 = 0.5f * v3 * (1.0f + erff(v3 * 0.70710678118654752f));
                *(__half2*)&Cout[(size_t)rr0 * Nn + cc]       = __floats2half2_rn(v0, v1);
                *(__half2*)&Cout[(size_t)(rr0 + 8) * Nn + cc] = __floats2half2_rn(v2, v3);
            }
        }
    }
}

// ---------------------------------------------------------------------------
// fp16 flash attention with permutation mask.
// 128 queries/block (8 warps x 16 rows), KV tiles of 64, D=64.
// NEW this round: base-2 softmax with ex2.approx.f16x2 producing P fragments
// directly, and row-sum l accumulated by an extra mma against an all-ones B
// fragment (lacc C-frag; no cross-lane sum reductions at all).
// ---------------------------------------------------------------------------
constexpr int KSH = 72;
constexpr int KV_TILE_B = 64 * KSH * 2;           // 9216 B
constexpr int KV_STAGE_B = 2 * KV_TILE_B;         // 18432 B
constexpr int PERM_OFF = 3 * KV_STAGE_B;          // 55296
constexpr int ATTN_SMEM = PERM_OFF + Tt * 4;      // 63488 B

__global__ __launch_bounds__(256, 2) void attn_mma(
    const __half* __restrict__ qkv, const int* __restrict__ perm,
    __half* __restrict__ out) {
    extern __shared__ __half smem_a[];
    uint32_t sb = smem_u32(smem_a);
    int* permS = (int*)((char*)smem_a + PERM_OFF);

    int tid = threadIdx.x, lane = tid & 31, w = tid >> 5;
    int r = lane >> 2, c = lane & 3;
    int q0 = blockIdx.x * 128;
    int h = blockIdx.y, b = blockIdx.z;

    int frow = ((lane >> 3) & 1) * 8 + (lane & 7);
    int fcol = (lane >> 4) * 8;

    #pragma unroll
    for (int i = 0; i < 2; i++)
        ((int4*)permS)[tid + i * 256] = ((const int4*)perm)[tid + i * 256];

    auto loadKV = [&](int st, int t) {
        int k0 = t * 64;
        uint32_t base = sb + (uint32_t)(st * KV_STAGE_B);
        #pragma unroll
        for (int i = 0; i < 4; i++) {
            int ch = tid + i * 256;
            int which = ch >> 9;
            int idx = ch & 511;
            int rr = idx >> 3, c8 = idx & 7;
            const __half* src = qkv + ((size_t)(b * Tt + k0 + rr)) * 3072
                              + (which ? 2048 : 1024) + h * 64 + c8 * 8;
            cp16(base + (uint32_t)(which * KV_TILE_B)
                      + (uint32_t)(rr * KSH + c8 * 8) * 2u, src);
        }
    };

    const __half* qb = qkv + ((size_t)(b * Tt + q0 + w * 16)) * 3072 + h * 64;
    uint32_t qa[4][4];
    #pragma unroll
    for (int j = 0; j < 4; j++) {
        qa[j][0] = *(const uint32_t*)&qb[(size_t)r * 3072 + j * 16 + 2 * c];
        qa[j][1] = *(const uint32_t*)&qb[(size_t)(r + 8) * 3072 + j * 16 + 2 * c];
        qa[j][2] = *(const uint32_t*)&qb[(size_t)r * 3072 + j * 16 + 8 + 2 * c];
        qa[j][3] = *(const uint32_t*)&qb[(size_t)(r + 8) * 3072 + j * 16 + 8 + 2 * c];
    }

    float oacc[8][4];
    #pragma unroll
    for (int i = 0; i < 8; i++)
        #pragma unroll
        for (int k = 0; k < 4; k++) oacc[i][k] = 0.f;
    float lacc[4] = {0.f, 0.f, 0.f, 0.f};     // row-sum accumulator (mma-ones)
    float m0 = -1e30f, m1 = -1e30f;
    int q_lo = q0 + w * 16 + r, q_hi = q_lo + 8;

    // scores scaled straight into log2 domain: 0.125 * log2(e)
    constexpr float SC2 = 0.18033688011112042f;

    constexpr int NT = Tt / 64;
    loadKV(0, 0);
    asm volatile("cp.async.commit_group;\n" ::: "memory");
    loadKV(1, 1);
    asm volatile("cp.async.commit_group;\n" ::: "memory");

    for (int t = 0; t < NT; t++) {
        int st = t % 3;
        asm volatile("cp.async.wait_group 1;\n" ::: "memory");
        __syncthreads();
        if (t + 2 < NT) loadKV((t + 2) % 3, t + 2);
        asm volatile("cp.async.commit_group;\n" ::: "memory");

        uint32_t ksBase = sb + (uint32_t)(st * KV_STAGE_B);
        uint32_t vsBase = ksBase + (uint32_t)KV_TILE_B;

        // S = Q @ K^T
        float sacc[8][4];
        #pragma unroll
        for (int i = 0; i < 8; i++)
            #pragma unroll
            for (int k = 0; k < 4; k++) sacc[i][k] = 0.f;
        #pragma unroll
        for (int j = 0; j < 4; j++) {
            #pragma unroll
            for (int np = 0; np < 4; np++) {
                uint32_t kb[4];
                ldsm_x4(kb, ksBase
                        + (uint32_t)((np * 16 + frow) * KSH + j * 16 + fcol) * 2u);
                mma_f16(sacc[np * 2],     qa[j], kb[0], kb[2]);
                mma_f16(sacc[np * 2 + 1], qa[j], kb[1], kb[3]);
            }
        }

        // Mask + log2-scale + per-row max
        const int* pT = permS + t * 64;
        float mx0 = -1e30f, mx1 = -1e30f;
        #pragma unroll
        for (int ni = 0; ni < 8; ni++) {
            int col = ni * 8 + 2 * c;
            int p0 = pT[col], p1 = pT[col + 1];
            sacc[ni][0] = (p0 > q_lo) ? -1e30f : sacc[ni][0] * SC2;
            sacc[ni][1] = (p1 > q_lo) ? -1e30f : sacc[ni][1] * SC2;
            sacc[ni][2] = (p0 > q_hi) ? -1e30f : sacc[ni][2] * SC2;
            sacc[ni][3] = (p1 > q_hi) ? -1e30f : sacc[ni][3] * SC2;
            mx0 = fmaxf(mx0, fmaxf(sacc[ni][0], sacc[ni][1]));
            mx1 = fmaxf(mx1, fmaxf(sacc[ni][2], sacc[ni][3]));
        }
        mx0 = fmaxf(mx0, __shfl_xor_sync(0xffffffffu, mx0, 1));
        mx0 = fmaxf(mx0, __shfl_xor_sync(0xffffffffu, mx0, 2));
        mx1 = fmaxf(mx1, __shfl_xor_sync(0xffffffffu, mx1, 1));
        mx1 = fmaxf(mx1, __shfl_xor_sync(0xffffffffu, mx1, 2));

        float nm0 = fmaxf(m0, mx0), nm1 = fmaxf(m1, mx1);
        float al0 = exp2f(m0 - nm0), al1 = exp2f(m1 - nm1);
        m0 = nm0; m1 = nm1;
        #pragma unroll
        for (int ni = 0; ni < 8; ni++) {
            oacc[ni][0] *= al0; oacc[ni][1] *= al0;
            oacc[ni][2] *= al1; oacc[ni][3] *= al1;
        }
        lacc[0] *= al0; lacc[1] *= al0;
        lacc[2] *= al1; lacc[3] *= al1;

        // P = 2^(x - m) packed as fp16x2 A-fragments; l += P @ ones; O += P @ V
        #pragma unroll
        for (int j = 0; j < 4; j++) {
            uint32_t pa[4];
            pa[0] = h2exp2_from(sacc[2 * j][0] - nm0,     sacc[2 * j][1] - nm0);
            pa[1] = h2exp2_from(sacc[2 * j][2] - nm1,     sacc[2 * j][3] - nm1);
            pa[2] = h2exp2_from(sacc[2 * j + 1][0] - nm0, sacc[2 * j + 1][1] - nm0);
            pa[3] = h2exp2_from(sacc[2 * j + 1][2] - nm1, sacc[2 * j + 1][3] - nm1);
            mma_f16(lacc, pa, ONES_H2, ONES_H2);
            #pragma unroll
            for (int db = 0; db < 4; db++) {
                uint32_t vb[4];
                ldsm_x4_t(vb, vsBase
                          + (uint32_t)((j * 16 + frow) * KSH + db * 16 + fcol) * 2u);
                mma_f16(oacc[db * 2],     pa, vb[0], vb[1]);
                mma_f16(oacc[db * 2 + 1], pa, vb[2], vb[3]);
            }
        }
    }

    float inv0 = 1.0f / lacc[0], inv1 = 1.0f / lacc[2];
    __half* ob = out + ((size_t)(b * Tt + q_lo)) * 1024 + h * 64;
    #pragma unroll
    for (int ni = 0; ni < 8; ni++) {
        int col = ni * 8 + 2 * c;
        *(__half2*)&ob[col] = __floats2half2_rn(oacc[ni][0] * inv0, oacc[ni][1] * inv0);
        *(__half2*)&ob[(size_t)8 * 1024 + col] =
            __floats2half2_rn(oacc[ni][2] * inv1, oacc[ni][3] * inv1);
    }
}

// ---------------------------------------------------------------------------
// Launch
// ---------------------------------------------------------------------------
extern "C" void kernel_launch(void* const* d_in, const int* in_sizes, int n_in,
                              void* d_out, int out_size) {
    (void)in_sizes; (void)n_in; (void)out_size;
    const float* x     = (const float*)d_in[0];
    const int*   perm  = (const int*)d_in[1];
    const float* Wqkv  = (const float*)d_in[2];
    const float* Wproj = (const float*)d_in[3];
    const float* bproj = (const float*)d_in[4];
    const float* ln1_g = (const float*)d_in[5];
    const float* ln1_b = (const float*)d_in[6];
    const float* ln2_g = (const float*)d_in[7];
    const float* ln2_b = (const float*)d_in[8];
    const float* Wff1  = (const float*)d_in[9];
    const float* bff1  = (const float*)d_in[10];
    const float* Wff2  = (const float*)d_in[11];
    const float* bff2  = (const float*)d_in[12];
    float* out = (float*)d_out;

    void *ph, *pqkv, *patt, *px2, *pff, *pwq, *pwp, *pw1, *pw2;
    cudaGetSymbolAddress(&ph,   g_h);
    cudaGetSymbolAddress(&pqkv, g_qkv);
    cudaGetSymbolAddress(&patt, g_att);
    cudaGetSymbolAddress(&px2,  g_x2);
    cudaGetSymbolAddress(&pff,  g_ff);
    cudaGetSymbolAddress(&pwq,  g_wqkvT);
    cudaGetSymbolAddress(&pwp,  g_wprojT);
    cudaGetSymbolAddress(&pw1,  g_wff1T);
    cudaGetSymbolAddress(&pw2,  g_wff2T);
    __half* h   = (__half*)ph;
    __half* qkv = (__half*)pqkv;
    __half* att = (__half*)patt;
    float*  x2  = (float*)px2;
    __half* ff  = (__half*)pff;
    __half* wqT = (__half*)pwq;
    __half* wpT = (__half*)pwp;
    __half* w1T = (__half*)pw1;
    __half* w2T = (__half*)pw2;

    cudaFuncSetAttribute((const void*)tgemm<0>,
                         cudaFuncAttributeMaxDynamicSharedMemorySize, GEMM_SMEM);
    cudaFuncSetAttribute((const void*)tgemm<1>,
                         cudaFuncAttributeMaxDynamicSharedMemorySize, GEMM_SMEM);
    cudaFuncSetAttribute((const void*)tgemm<2>,
                         cudaFuncAttributeMaxDynamicSharedMemorySize, GEMM_SMEM);
    cudaFuncSetAttribute((const void*)attn_mma,
                         cudaFuncAttributeMaxDynamicSharedMemorySize, ATTN_SMEM);

    // 0. Weight transpose + fp16 convert (single launch)
    round_wT_all<<<8192, dim3(32, 8)>>>(Wqkv, wqT, Wproj, wpT, Wff1, w1T, Wff2, w2T);

    // 1. h = LN1(x)
    ln_kernel<<<Mm, 256>>>(x, ln1_g, ln1_b, h);
    // 2. qkv = h @ Wqkv
    tgemm<0><<<dim3(3 * Cc / 128, Mm / 128), 256, GEMM_SMEM>>>(
        h, wqT, nullptr, nullptr, qkv, Mm, 3 * Cc, Cc);
    // 3. attention -> att
    attn_mma<<<dim3(Tt / 128, Hh, Bb), 256, ATTN_SMEM>>>(qkv, perm, att);
    // 4. x2 = x + att @ Wproj + bproj
    tgemm<1><<<dim3(Cc / 128, Mm / 128), 256, GEMM_SMEM>>>(
        att, wpT, bproj, x, x2, Mm, Cc, Cc);
    // 5. h = LN2(x2)
    ln_kernel<<<Mm, 256>>>(x2, ln2_g, ln2_b, h);
    // 6. ff = gelu(h @ Wff1 + bff1)
    tgemm<2><<<dim3(FFf / 128, Mm / 128), 256, GEMM_SMEM>>>(
        h, w1T, bff1, nullptr, ff, Mm, FFf, Cc);
    // 7. out = x2 + ff @ Wff2 + bff2
    tgemm<1><<<dim3(Cc / 128, Mm / 128), 256, GEMM_SMEM>>>(
        ff, w2T, bff2, x2, out, Mm, Cc, FFf);
}